// round 1
// baseline (speedup 1.0000x reference)
#include <cuda_runtime.h>
#include <math.h>

#define B 4
#define S 2048
#define E 256
#define H 8
#define D 32
#define M (B*S)

// ---------------- scratch (device globals; no allocation allowed) ----------
static __device__ __align__(16) float g_Q[M*E];
static __device__ __align__(16) float g_K[M*E];
static __device__ __align__(16) float g_V[M*E];
static __device__ __align__(16) float g_pad[M*E];
static __device__ int g_len[B];

// ---------------- lengths: mask is a binary prefix mask ---------------------
__global__ void len_kernel(const int* __restrict__ mask) {
    int b = blockIdx.x;
    int t = threadIdx.x;
    int s = 0;
    for (int i = t; i < S; i += 256) s += mask[b*S + i];
    __shared__ int sh[256];
    sh[t] = s;
    __syncthreads();
    for (int o = 128; o > 0; o >>= 1) {
        if (t < o) sh[t] += sh[t + o];
        __syncthreads();
    }
    if (t == 0) g_len[b] = sh[0];
}

// ---------------- fp32 NT GEMM: Y[m,n] = sum_k X[m,k] * W[n,k] --------------
// M_ rows, N=E cols, K=E. 64x64 tile, 16-deep k slab, 4x4 per-thread microtile.
__global__ __launch_bounds__(256)
void gemm_nt64(const float* __restrict__ Xg, const float* __restrict__ Wg,
               float* __restrict__ Yg) {
    __shared__ float xs[16][65];
    __shared__ float ws[16][65];
    const int bm = blockIdx.x * 64;
    const int bn = blockIdx.y * 64;
    const int tid = threadIdx.x;
    const int tx = tid & 15;
    const int ty = tid >> 4;
    float acc[4][4] = {};

    for (int k0 = 0; k0 < E; k0 += 16) {
        #pragma unroll
        for (int i = 0; i < 4; i++) {
            int idx = tid + i * 256;       // 0..1023
            int r = idx >> 4;              // 0..63
            int c = idx & 15;              // 0..15
            xs[c][r] = Xg[(bm + r) * E + k0 + c];
            ws[c][r] = Wg[(bn + r) * E + k0 + c];
        }
        __syncthreads();
        #pragma unroll
        for (int kk = 0; kk < 16; kk++) {
            float a[4], w[4];
            #pragma unroll
            for (int i = 0; i < 4; i++) a[i] = xs[kk][ty*4 + i];
            #pragma unroll
            for (int j = 0; j < 4; j++) w[j] = ws[kk][tx*4 + j];
            #pragma unroll
            for (int i = 0; i < 4; i++)
                #pragma unroll
                for (int j = 0; j < 4; j++)
                    acc[i][j] += a[i] * w[j];
        }
        __syncthreads();
    }
    #pragma unroll
    for (int i = 0; i < 4; i++)
        #pragma unroll
        for (int j = 0; j < 4; j++)
            Yg[(bm + ty*4 + i) * E + bn + tx*4 + j] = acc[i][j];
}

// ---------------- varlen flash attention, output in scrambled layout --------
// One thread = one query row. Block = 128 queries of one (b,h).
// Writes attn output directly at padded flat index (h*L + q)*D + d, q < L.
__global__ __launch_bounds__(128)
void attn_kernel() {
    const int b = blockIdx.z;
    const int h = blockIdx.y;
    const int L = g_len[b];
    const int q = blockIdx.x * 128 + threadIdx.x;
    if (blockIdx.x * 128 >= L) return;         // uniform block exit
    const bool active = (q < L);

    __shared__ __align__(16) float Ks[32][32];
    __shared__ __align__(16) float Vs[32][32];

    float qv[32];
    if (active) {
        const float4* qp = (const float4*)&g_Q[((size_t)(b*S + q)*H + h)*D];
        #pragma unroll
        for (int i = 0; i < 8; i++) {
            float4 v = qp[i];
            qv[4*i+0]=v.x; qv[4*i+1]=v.y; qv[4*i+2]=v.z; qv[4*i+3]=v.w;
        }
    } else {
        #pragma unroll
        for (int i = 0; i < 32; i++) qv[i] = 0.f;
    }

    float mx = -1e30f, l = 0.f;
    float acc[32];
    #pragma unroll
    for (int i = 0; i < 32; i++) acc[i] = 0.f;
    const float scale = 0.17677669529663687f;  // 1/sqrt(32)

    for (int k0 = 0; k0 < L; k0 += 32) {
        const int tn = min(32, L - k0);
        // cooperative tile load: 32 keys x 32 floats for K and V
        #pragma unroll
        for (int i = 0; i < 2; i++) {
            int idx = threadIdx.x + i * 128;   // 0..255
            int r = idx >> 3;                  // 0..31
            int c = idx & 7;                   // 0..7 (float4 lanes)
            if (r < tn) {
                const float4* kp = (const float4*)&g_K[((size_t)(b*S + k0 + r)*H + h)*D];
                ((float4*)Ks[r])[c] = kp[c];
                const float4* vp = (const float4*)&g_V[((size_t)(b*S + k0 + r)*H + h)*D];
                ((float4*)Vs[r])[c] = vp[c];
            }
        }
        __syncthreads();

        for (int kk = 0; kk < tn; kk++) {
            float s = 0.f;
            const float4* kr = (const float4*)Ks[kk];
            #pragma unroll
            for (int i = 0; i < 8; i++) {
                float4 kv = kr[i];
                s += qv[4*i+0]*kv.x + qv[4*i+1]*kv.y
                   + qv[4*i+2]*kv.z + qv[4*i+3]*kv.w;
            }
            s *= scale;
            if (s > mx) {                        // rare rescale (~ln L times)
                float c = __expf(mx - s);
                l *= c;
                #pragma unroll
                for (int i = 0; i < 32; i++) acc[i] *= c;
                mx = s;
            }
            float p = __expf(s - mx);
            l += p;
            const float4* vr = (const float4*)Vs[kk];
            #pragma unroll
            for (int i = 0; i < 8; i++) {
                float4 vv = vr[i];
                acc[4*i+0] += p*vv.x; acc[4*i+1] += p*vv.y;
                acc[4*i+2] += p*vv.z; acc[4*i+3] += p*vv.w;
            }
        }
        __syncthreads();
    }

    if (active) {
        float inv = 1.f / l;
        // scrambled-pad bijection: flat = h*L*D + q*D + d
        float4* o4 = (float4*)&g_pad[(size_t)b*S*E + ((size_t)h*L + q)*D];
        #pragma unroll
        for (int i = 0; i < 8; i++) {
            float4 v;
            v.x = acc[4*i+0]*inv; v.y = acc[4*i+1]*inv;
            v.z = acc[4*i+2]*inv; v.w = acc[4*i+3]*inv;
            o4[i] = v;
        }
    }
}

// ---------------- launch ----------------------------------------------------
extern "C" void kernel_launch(void* const* d_in, const int* in_sizes, int n_in,
                              void* d_out, int out_size) {
    const float* x    = (const float*)d_in[0];
    const int*   mask = (const int*)  d_in[1];
    const float* Wq   = (const float*)d_in[2];
    const float* Wk   = (const float*)d_in[3];
    const float* Wv   = (const float*)d_in[4];
    const float* Wo   = (const float*)d_in[5];
    float* out = (float*)d_out;

    float *Qp, *Kp, *Vp, *Pp;
    cudaGetSymbolAddress((void**)&Qp, g_Q);
    cudaGetSymbolAddress((void**)&Kp, g_K);
    cudaGetSymbolAddress((void**)&Vp, g_V);
    cudaGetSymbolAddress((void**)&Pp, g_pad);

    len_kernel<<<B, 256>>>(mask);
    cudaMemsetAsync(Pp, 0, (size_t)M * E * sizeof(float), 0);

    dim3 gg(M / 64, E / 64);
    gemm_nt64<<<gg, 256>>>(x, Wq, Qp);
    gemm_nt64<<<gg, 256>>>(x, Wk, Kp);
    gemm_nt64<<<gg, 256>>>(x, Wv, Vp);

    dim3 ga(S / 128, H, B);
    attn_kernel<<<ga, 128>>>();

    gemm_nt64<<<gg, 256>>>(Pp, Wo, out);
}

// round 3
// speedup vs baseline: 1.2855x; 1.2855x over previous
#include <cuda_runtime.h>
#include <cuda_bf16.h>
#include <stdint.h>

#define B 4
#define S 2048
#define E 256
#define H 8
#define D 32
#define M (B*S)

// ---------------- scratch (device globals; no allocation allowed) ----------
static __device__ __align__(16) float g_Q[M*E];
static __device__ __align__(16) float g_K[M*E];
static __device__ __align__(16) float g_V[M*E];
static __device__ __align__(16) float g_pad[M*E];
static __device__ __align__(16) __nv_bfloat16 g_xhi[M*E];
static __device__ __align__(16) __nv_bfloat16 g_xlo[M*E];
static __device__ __align__(16) __nv_bfloat16 g_phi[M*E];
static __device__ __align__(16) __nv_bfloat16 g_plo[M*E];
static __device__ __align__(16) __nv_bfloat16 g_whi[4*E*E];
static __device__ __align__(16) __nv_bfloat16 g_wlo[4*E*E];
static __device__ int g_len[B];

// ---------------- helpers ----------------------------------------------------
__device__ __forceinline__ uint32_t smem_u32(const void* p) {
    uint32_t a;
    asm("{ .reg .u64 t; cvta.to.shared.u64 t, %1; cvt.u32.u64 %0, t; }"
        : "=r"(a) : "l"(p));
    return a;
}

__device__ __forceinline__ void ldsm4(uint32_t* r, uint32_t addr) {
    asm volatile("ldmatrix.sync.aligned.m8n8.x4.shared.b16 {%0,%1,%2,%3}, [%4];"
                 : "=r"(r[0]), "=r"(r[1]), "=r"(r[2]), "=r"(r[3]) : "r"(addr));
}

__device__ __forceinline__ void mma16816(float* d, const uint32_t* a, const uint32_t* b) {
    asm volatile(
        "mma.sync.aligned.m16n8k16.row.col.f32.bf16.bf16.f32 "
        "{%0,%1,%2,%3}, {%4,%5,%6,%7}, {%8,%9}, {%0,%1,%2,%3};"
        : "+f"(d[0]), "+f"(d[1]), "+f"(d[2]), "+f"(d[3])
        : "r"(a[0]), "r"(a[1]), "r"(a[2]), "r"(a[3]), "r"(b[0]), "r"(b[1]));
}

// ---------------- lengths ----------------------------------------------------
__global__ void len_kernel(const int* __restrict__ mask) {
    int b = blockIdx.x;
    int t = threadIdx.x;
    int s = 0;
    for (int i = t; i < S; i += 256) s += mask[b*S + i];
    __shared__ int sh[256];
    sh[t] = s;
    __syncthreads();
    for (int o = 128; o > 0; o >>= 1) {
        if (t < o) sh[t] += sh[t + o];
        __syncthreads();
    }
    if (t == 0) g_len[b] = sh[0];
}

// ---------------- fp32 -> bf16 hi/lo decomposition ---------------------------
__global__ __launch_bounds__(256)
void decomp_kernel(const float* __restrict__ x, __nv_bfloat16* __restrict__ hi,
                   __nv_bfloat16* __restrict__ lo, int n4) {
    int i = blockIdx.x * 256 + threadIdx.x;
    if (i >= n4) return;
    float4 v = ((const float4*)x)[i];
    float f[4] = {v.x, v.y, v.z, v.w};
    #pragma unroll
    for (int j = 0; j < 4; j++) {
        __nv_bfloat16 h = __float2bfloat16(f[j]);
        hi[4*i + j] = h;
        lo[4*i + j] = __float2bfloat16(f[j] - __bfloat162float(h));
    }
}

// ---------------- mma.sync bf16x3 GEMM: Y[m,n] = sum_k X[m,k] W[n,k] ---------
// CTA: 128x128 tile, 512 threads = 16 warps (4x4), warp tile 32x32.
// K=256 in 4 chunks of 64 staged through smem; row pitch 144B (ldmatrix
// conflict-free: row offsets mod 128 = {0,16,...,112}).
#define GPITCH 144
#define GCHUNKB (128 * GPITCH)                 // 18432 bytes per array
#define GEMM_SMEM (4 * GCHUNKB)                // Ahi,Alo,Bhi,Blo

__global__ __launch_bounds__(512, 1)
void gemm_mma(const __nv_bfloat16* __restrict__ Ahi, const __nv_bfloat16* __restrict__ Alo,
              const __nv_bfloat16* __restrict__ Bhi, const __nv_bfloat16* __restrict__ Blo,
              float* __restrict__ Yg) {
    extern __shared__ char smem[];
    const int bm = blockIdx.x * 128;
    const int bn = blockIdx.y * 128;
    const int tid = threadIdx.x;
    const int lane = tid & 31;
    const int wid = tid >> 5;
    const int wm = (wid & 3) * 32;
    const int wn = (wid >> 2) * 32;

    char* sAhi = smem;
    char* sAlo = smem + GCHUNKB;
    char* sBhi = smem + 2 * GCHUNKB;
    char* sBlo = smem + 3 * GCHUNKB;
    const uint32_t uAhi = smem_u32(sAhi);
    const uint32_t uAlo = uAhi + GCHUNKB;
    const uint32_t uBhi = uAhi + 2 * GCHUNKB;
    const uint32_t uBlo = uAhi + 3 * GCHUNKB;

    float acc[2][4][4];
    #pragma unroll
    for (int mi = 0; mi < 2; mi++)
        #pragma unroll
        for (int ni = 0; ni < 4; ni++)
            #pragma unroll
            for (int k = 0; k < 4; k++) acc[mi][ni][k] = 0.f;

    // ldmatrix per-thread address offsets (within a tile, before k/row bases)
    const int a_row = (lane & 7) + ((lane >> 3) & 1) * 8;   // + row0
    const int a_kb  = (lane >> 4) * 16;                     // byte offset in k
    const int b_row = (lane & 7) + (lane >> 4) * 8;         // + n0
    const int b_kb  = ((lane >> 3) & 1) * 16;

    for (int kc = 0; kc < 4; kc++) {
        const int k0 = kc * 64;
        // stage 128x64 bf16 of each of the 4 arrays
        #pragma unroll
        for (int i = 0; i < 2; i++) {
            int u = tid + i * 512;               // 0..1023
            int r = u >> 3, c = u & 7;           // row, float4-col
            size_t goff = (size_t)r * E + k0 + c * 8;
            int soff = r * GPITCH + c * 16;
            *(float4*)(sAhi + soff) = *(const float4*)(Ahi + (size_t)bm * E + goff);
            *(float4*)(sAlo + soff) = *(const float4*)(Alo + (size_t)bm * E + goff);
            *(float4*)(sBhi + soff) = *(const float4*)(Bhi + (size_t)bn * E + goff);
            *(float4*)(sBlo + soff) = *(const float4*)(Blo + (size_t)bn * E + goff);
        }
        __syncthreads();

        #pragma unroll
        for (int ks = 0; ks < 4; ks++) {
            const int kb = ks * 32;              // byte offset of this k16 step
            uint32_t ahi[2][4], alo[2][4], bhi[4][2], blo[4][2];
            #pragma unroll
            for (int mi = 0; mi < 2; mi++) {
                uint32_t off = (uint32_t)((wm + mi * 16 + a_row) * GPITCH + kb + a_kb);
                ldsm4(ahi[mi], uAhi + off);
                ldsm4(alo[mi], uAlo + off);
            }
            #pragma unroll
            for (int np = 0; np < 2; np++) {
                uint32_t off = (uint32_t)((wn + np * 16 + b_row) * GPITCH + kb + b_kb);
                uint32_t th[4], tl[4];
                ldsm4(th, uBhi + off);
                ldsm4(tl, uBlo + off);
                bhi[np*2][0] = th[0]; bhi[np*2][1] = th[1];
                bhi[np*2+1][0] = th[2]; bhi[np*2+1][1] = th[3];
                blo[np*2][0] = tl[0]; blo[np*2][1] = tl[1];
                blo[np*2+1][0] = tl[2]; blo[np*2+1][1] = tl[3];
            }
            #pragma unroll
            for (int mi = 0; mi < 2; mi++)
                #pragma unroll
                for (int ni = 0; ni < 4; ni++) {
                    mma16816(acc[mi][ni], ahi[mi], bhi[ni]);
                    mma16816(acc[mi][ni], ahi[mi], blo[ni]);
                    mma16816(acc[mi][ni], alo[mi], bhi[ni]);
                }
        }
        __syncthreads();
    }

    // store: c0,c1 -> (row g, col tig*2..+1); c2,c3 -> row g+8
    const int g = lane >> 2;
    const int tg2 = (lane & 3) * 2;
    #pragma unroll
    for (int mi = 0; mi < 2; mi++)
        #pragma unroll
        for (int ni = 0; ni < 4; ni++) {
            int row = bm + wm + mi * 16 + g;
            int col = bn + wn + ni * 8 + tg2;
            *(float2*)&Yg[(size_t)row * E + col] =
                make_float2(acc[mi][ni][0], acc[mi][ni][1]);
            *(float2*)&Yg[(size_t)(row + 8) * E + col] =
                make_float2(acc[mi][ni][2], acc[mi][ni][3]);
        }
}

// ---------------- varlen flash attention, scrambled-layout output ------------
__global__ __launch_bounds__(128)
void attn_kernel() {
    const int b = blockIdx.z;
    const int h = blockIdx.y;
    const int L = g_len[b];
    const int q = blockIdx.x * 128 + threadIdx.x;
    if (blockIdx.x * 128 >= L) return;
    const bool active = (q < L);

    __shared__ __align__(16) float Ks[64][32];
    __shared__ __align__(16) float Vs[64][32];

    float qv[32];
    if (active) {
        const float4* qp = (const float4*)&g_Q[((size_t)(b*S + q)*H + h)*D];
        #pragma unroll
        for (int i = 0; i < 8; i++) {
            float4 v = qp[i];
            qv[4*i+0]=v.x; qv[4*i+1]=v.y; qv[4*i+2]=v.z; qv[4*i+3]=v.w;
        }
    } else {
        #pragma unroll
        for (int i = 0; i < 32; i++) qv[i] = 0.f;
    }

    float mx = -1e30f, l = 0.f;
    float acc[32];
    #pragma unroll
    for (int i = 0; i < 32; i++) acc[i] = 0.f;
    const float scale = 0.17677669529663687f;  // 1/sqrt(32)

    for (int k0 = 0; k0 < L; k0 += 64) {
        const int tn = min(64, L - k0);
        #pragma unroll
        for (int i = 0; i < 4; i++) {
            int idx = threadIdx.x + i * 128;   // 0..511
            int r = idx >> 3;
            int c = idx & 7;
            if (r < tn) {
                const float4* kp = (const float4*)&g_K[((size_t)(b*S + k0 + r)*H + h)*D];
                ((float4*)Ks[r])[c] = kp[c];
                const float4* vp = (const float4*)&g_V[((size_t)(b*S + k0 + r)*H + h)*D];
                ((float4*)Vs[r])[c] = vp[c];
            }
        }
        __syncthreads();

        for (int kk = 0; kk < tn; kk++) {
            float s0 = 0.f, s1 = 0.f, s2 = 0.f, s3 = 0.f;
            const float4* kr = (const float4*)Ks[kk];
            #pragma unroll
            for (int i = 0; i < 8; i++) {
                float4 kv = kr[i];
                s0 += qv[4*i+0]*kv.x; s1 += qv[4*i+1]*kv.y;
                s2 += qv[4*i+2]*kv.z; s3 += qv[4*i+3]*kv.w;
            }
            float s = ((s0 + s1) + (s2 + s3)) * scale;
            if (s > mx) {
                float c = __expf(mx - s);
                l *= c;
                #pragma unroll
                for (int i = 0; i < 32; i++) acc[i] *= c;
                mx = s;
            }
            float p = __expf(s - mx);
            l += p;
            const float4* vr = (const float4*)Vs[kk];
            #pragma unroll
            for (int i = 0; i < 8; i++) {
                float4 vv = vr[i];
                acc[4*i+0] += p*vv.x; acc[4*i+1] += p*vv.y;
                acc[4*i+2] += p*vv.z; acc[4*i+3] += p*vv.w;
            }
        }
        __syncthreads();
    }

    if (active) {
        float inv = 1.f / l;
        float4* o4 = (float4*)&g_pad[(size_t)b*S*E + ((size_t)h*L + q)*D];
        #pragma unroll
        for (int i = 0; i < 8; i++) {
            float4 v;
            v.x = acc[4*i+0]*inv; v.y = acc[4*i+1]*inv;
            v.z = acc[4*i+2]*inv; v.w = acc[4*i+3]*inv;
            o4[i] = v;
        }
    }
}

// ---------------- launch ------------------------------------------------------
extern "C" void kernel_launch(void* const* d_in, const int* in_sizes, int n_in,
                              void* d_out, int out_size) {
    const float* x    = (const float*)d_in[0];
    const int*   mask = (const int*)  d_in[1];
    const float* W[4] = { (const float*)d_in[2], (const float*)d_in[3],
                          (const float*)d_in[4], (const float*)d_in[5] };
    float* out = (float*)d_out;

    float *Qp, *Kp, *Vp, *Pp;
    __nv_bfloat16 *xhi, *xlo, *phi, *plo, *whi, *wlo;
    cudaGetSymbolAddress((void**)&Qp, g_Q);
    cudaGetSymbolAddress((void**)&Kp, g_K);
    cudaGetSymbolAddress((void**)&Vp, g_V);
    cudaGetSymbolAddress((void**)&Pp, g_pad);
    cudaGetSymbolAddress((void**)&xhi, g_xhi);
    cudaGetSymbolAddress((void**)&xlo, g_xlo);
    cudaGetSymbolAddress((void**)&phi, g_phi);
    cudaGetSymbolAddress((void**)&plo, g_plo);
    cudaGetSymbolAddress((void**)&whi, g_whi);
    cudaGetSymbolAddress((void**)&wlo, g_wlo);

    cudaFuncSetAttribute(gemm_mma, cudaFuncAttributeMaxDynamicSharedMemorySize,
                         GEMM_SMEM);

    len_kernel<<<B, 256>>>(mask);
    cudaMemsetAsync(Pp, 0, (size_t)M * E * sizeof(float), 0);

    decomp_kernel<<<(M*E/4 + 255)/256, 256>>>(x, xhi, xlo, M*E/4);
    for (int w = 0; w < 4; w++)
        decomp_kernel<<<(E*E/4 + 255)/256, 256>>>(W[w], whi + w*E*E, wlo + w*E*E, E*E/4);

    dim3 gg(M / 128, E / 128);
    gemm_mma<<<gg, 512, GEMM_SMEM>>>(xhi, xlo, whi + 0*E*E, wlo + 0*E*E, Qp);
    gemm_mma<<<gg, 512, GEMM_SMEM>>>(xhi, xlo, whi + 1*E*E, wlo + 1*E*E, Kp);
    gemm_mma<<<gg, 512, GEMM_SMEM>>>(xhi, xlo, whi + 2*E*E, wlo + 2*E*E, Vp);

    dim3 ga(S / 128, H, B);
    attn_kernel<<<ga, 128>>>();

    decomp_kernel<<<(M*E/4 + 255)/256, 256>>>(Pp, phi, plo, M*E/4);
    gemm_mma<<<gg, 512, GEMM_SMEM>>>(phi, plo, whi + 3*E*E, wlo + 3*E*E, out);
}

// round 5
// speedup vs baseline: 3.5465x; 2.7589x over previous
#include <cuda_runtime.h>
#include <cuda_bf16.h>
#include <stdint.h>

#define B 4
#define S 2048
#define E 256
#define H 8
#define D 32
#define M (B*S)
// SCALE * log2(e), folded into Wq at decomposition time
#define CEXP (0.17677669529663687f * 1.44269504088896341f)

// ---------------- scratch (device globals; no allocation allowed) ----------
static __device__ __align__(16) __nv_bfloat16 g_xhi[M*E];
static __device__ __align__(16) __nv_bfloat16 g_xlo[M*E];
static __device__ __align__(16) __nv_bfloat16 g_qhi[M*E];
static __device__ __align__(16) __nv_bfloat16 g_qlo[M*E];
static __device__ __align__(16) __nv_bfloat16 g_khi[M*E];
static __device__ __align__(16) __nv_bfloat16 g_klo[M*E];
static __device__ __align__(16) __nv_bfloat16 g_vhi[M*E];
static __device__ __align__(16) __nv_bfloat16 g_vlo[M*E];
static __device__ __align__(16) __nv_bfloat16 g_phi[M*E];
static __device__ __align__(16) __nv_bfloat16 g_plo[M*E];
static __device__ __align__(16) __nv_bfloat16 g_whi[4*E*E];
static __device__ __align__(16) __nv_bfloat16 g_wlo[4*E*E];
static __device__ int g_len[B];

// ---------------- helpers ----------------------------------------------------
__device__ __forceinline__ uint32_t smem_u32(const void* p) {
    uint32_t a;
    asm("{ .reg .u64 t; cvta.to.shared.u64 t, %1; cvt.u32.u64 %0, t; }"
        : "=r"(a) : "l"(p));
    return a;
}

__device__ __forceinline__ void ldsm4(uint32_t* r, uint32_t addr) {
    asm volatile("ldmatrix.sync.aligned.m8n8.x4.shared.b16 {%0,%1,%2,%3}, [%4];"
                 : "=r"(r[0]), "=r"(r[1]), "=r"(r[2]), "=r"(r[3]) : "r"(addr));
}

__device__ __forceinline__ void mma16816(float* d, const uint32_t* a,
                                         uint32_t b0, uint32_t b1) {
    asm volatile(
        "mma.sync.aligned.m16n8k16.row.col.f32.bf16.bf16.f32 "
        "{%0,%1,%2,%3}, {%4,%5,%6,%7}, {%8,%9}, {%0,%1,%2,%3};"
        : "+f"(d[0]), "+f"(d[1]), "+f"(d[2]), "+f"(d[3])
        : "r"(a[0]), "r"(a[1]), "r"(a[2]), "r"(a[3]), "r"(b0), "r"(b1));
}

__device__ __forceinline__ float ex2(float x) {
    float y;
    asm("ex2.approx.ftz.f32 %0, %1;" : "=f"(y) : "f"(x));
    return y;
}

// pack (a -> low, b -> high) as bf16x2, plus residual lo pair
__device__ __forceinline__ void split_pair(float a, float b,
                                           uint32_t& hi, uint32_t& lo) {
    uint32_t h;
    asm("cvt.rn.bf16x2.f32 %0, %1, %2;" : "=r"(h) : "f"(b), "f"(a));
    float ha = __uint_as_float(h << 16);
    float hb = __uint_as_float(h & 0xffff0000u);
    uint32_t l;
    asm("cvt.rn.bf16x2.f32 %0, %1, %2;" : "=r"(l) : "f"(b - hb), "f"(a - ha));
    hi = h;
    lo = l;
}

// ---------------- lengths ----------------------------------------------------
__global__ void len_kernel(const int* __restrict__ mask) {
    int b = blockIdx.x;
    int t = threadIdx.x;
    int s = 0;
    for (int i = t; i < S; i += 256) s += mask[b*S + i];
    __shared__ int sh[256];
    sh[t] = s;
    __syncthreads();
    for (int o = 128; o > 0; o >>= 1) {
        if (t < o) sh[t] += sh[t + o];
        __syncthreads();
    }
    if (t == 0) g_len[b] = sh[0];
}

// ---------------- fp32 -> bf16 hi/lo decomposition ---------------------------
__global__ __launch_bounds__(256)
void decomp_kernel(const float* __restrict__ x, __nv_bfloat16* __restrict__ hi,
                   __nv_bfloat16* __restrict__ lo, int n4) {
    int i = blockIdx.x * 256 + threadIdx.x;
    if (i >= n4) return;
    float4 v = ((const float4*)x)[i];
    float f[4] = {v.x, v.y, v.z, v.w};
    #pragma unroll
    for (int j = 0; j < 4; j++) {
        __nv_bfloat16 h = __float2bfloat16(f[j]);
        hi[4*i + j] = h;
        lo[4*i + j] = __float2bfloat16(f[j] - __bfloat162float(h));
    }
}

// all 4 weight matrices in one launch; Wq (y==0) pre-scaled by CEXP
__global__ __launch_bounds__(256)
void decompw_kernel(const float* __restrict__ w0, const float* __restrict__ w1,
                    const float* __restrict__ w2, const float* __restrict__ w3,
                    __nv_bfloat16* __restrict__ hi, __nv_bfloat16* __restrict__ lo) {
    int m = blockIdx.y;
    const float* src = (m == 0) ? w0 : (m == 1) ? w1 : (m == 2) ? w2 : w3;
    float sc = (m == 0) ? CEXP : 1.0f;
    int i = blockIdx.x * 256 + threadIdx.x;           // over E*E/4
    float4 v = ((const float4*)src)[i];
    float f[4] = {v.x * sc, v.y * sc, v.z * sc, v.w * sc};
    size_t base = (size_t)m * E * E + 4 * (size_t)i;
    #pragma unroll
    for (int j = 0; j < 4; j++) {
        __nv_bfloat16 h = __float2bfloat16(f[j]);
        hi[base + j] = h;
        lo[base + j] = __float2bfloat16(f[j] - __bfloat162float(h));
    }
}

// ---------------- mma.sync bf16x3 GEMM: Y[m,n] = sum_k X[m,k] W[n,k] ---------
// CTA 128x128, 512 threads, warp tile 32x32, K chunks of 64 via smem (pitch 144).
#define GPITCH 144
#define GCHUNKB (128 * GPITCH)
#define GEMM_SMEM (4 * GCHUNKB)

__global__ __launch_bounds__(512, 1)
void gemm_mma(const __nv_bfloat16* __restrict__ Ahi, const __nv_bfloat16* __restrict__ Alo,
              const __nv_bfloat16* __restrict__ Bhi, const __nv_bfloat16* __restrict__ Blo,
              float* __restrict__ Yf,
              __nv_bfloat16* __restrict__ Yhi, __nv_bfloat16* __restrict__ Ylo) {
    extern __shared__ char smem[];
    const int bm = blockIdx.x * 128;
    const int bn = blockIdx.y * 128;
    const int tid = threadIdx.x;
    const int lane = tid & 31;
    const int wid = tid >> 5;
    const int wm = (wid & 3) * 32;
    const int wn = (wid >> 2) * 32;

    char* sAhi = smem;
    char* sAlo = smem + GCHUNKB;
    char* sBhi = smem + 2 * GCHUNKB;
    char* sBlo = smem + 3 * GCHUNKB;
    const uint32_t uAhi = smem_u32(sAhi);
    const uint32_t uBhi = uAhi + 2 * GCHUNKB;

    float acc[2][4][4];
    #pragma unroll
    for (int mi = 0; mi < 2; mi++)
        #pragma unroll
        for (int ni = 0; ni < 4; ni++)
            #pragma unroll
            for (int k = 0; k < 4; k++) acc[mi][ni][k] = 0.f;

    const int a_row = lane & 15;
    const int a_kb  = (lane >> 4) * 16;

    for (int kc = 0; kc < 4; kc++) {
        const int k0 = kc * 64;
        #pragma unroll
        for (int i = 0; i < 2; i++) {
            int u = tid + i * 512;
            int r = u >> 3, c = u & 7;
            size_t goff = (size_t)r * E + k0 + c * 8;
            int soff = r * GPITCH + c * 16;
            *(float4*)(sAhi + soff) = *(const float4*)(Ahi + (size_t)bm * E + goff);
            *(float4*)(sAlo + soff) = *(const float4*)(Alo + (size_t)bm * E + goff);
            *(float4*)(sBhi + soff) = *(const float4*)(Bhi + (size_t)bn * E + goff);
            *(float4*)(sBlo + soff) = *(const float4*)(Blo + (size_t)bn * E + goff);
        }
        __syncthreads();

        #pragma unroll
        for (int ks = 0; ks < 4; ks++) {
            const int kb = ks * 32;
            uint32_t ahi[2][4], alo[2][4], bhi[4][2], blo[4][2];
            #pragma unroll
            for (int mi = 0; mi < 2; mi++) {
                uint32_t off = (uint32_t)((wm + mi * 16 + a_row) * GPITCH + kb + a_kb);
                ldsm4(ahi[mi], uAhi + off);
                ldsm4(alo[mi], uAhi + GCHUNKB + off);
            }
            #pragma unroll
            for (int np = 0; np < 2; np++) {
                uint32_t off = (uint32_t)((wn + np * 16 + a_row) * GPITCH + kb + a_kb);
                uint32_t th[4], tl[4];
                ldsm4(th, uBhi + off);
                ldsm4(tl, uBhi + GCHUNKB + off);
                bhi[np*2][0] = th[0]; bhi[np*2][1] = th[2];
                bhi[np*2+1][0] = th[1]; bhi[np*2+1][1] = th[3];
                blo[np*2][0] = tl[0]; blo[np*2][1] = tl[2];
                blo[np*2+1][0] = tl[1]; blo[np*2+1][1] = tl[3];
            }
            #pragma unroll
            for (int mi = 0; mi < 2; mi++)
                #pragma unroll
                for (int ni = 0; ni < 4; ni++) {
                    mma16816(acc[mi][ni], ahi[mi], bhi[ni][0], bhi[ni][1]);
                    mma16816(acc[mi][ni], ahi[mi], blo[ni][0], blo[ni][1]);
                    mma16816(acc[mi][ni], alo[mi], bhi[ni][0], bhi[ni][1]);
                }
        }
        __syncthreads();
    }

    const int g = lane >> 2;
    const int t2 = (lane & 3) * 2;
    #pragma unroll
    for (int mi = 0; mi < 2; mi++)
        #pragma unroll
        for (int ni = 0; ni < 4; ni++) {
            int row = bm + wm + mi * 16 + g;
            int col = bn + wn + ni * 8 + t2;
            if (Yf) {
                *(float2*)&Yf[(size_t)row * E + col] =
                    make_float2(acc[mi][ni][0], acc[mi][ni][1]);
                *(float2*)&Yf[(size_t)(row + 8) * E + col] =
                    make_float2(acc[mi][ni][2], acc[mi][ni][3]);
            } else {
                uint32_t h0, l0, h1, l1;
                split_pair(acc[mi][ni][0], acc[mi][ni][1], h0, l0);
                split_pair(acc[mi][ni][2], acc[mi][ni][3], h1, l1);
                *(uint32_t*)(Yhi + (size_t)row * E + col) = h0;
                *(uint32_t*)(Ylo + (size_t)row * E + col) = l0;
                *(uint32_t*)(Yhi + (size_t)(row + 8) * E + col) = h1;
                *(uint32_t*)(Ylo + (size_t)(row + 8) * E + col) = l1;
            }
        }
}

// ---------------- tensor-core varlen flash attention --------------------------
// CTA: 128 queries of one (b,h); 4 warps x 32 q-rows; key tiles of 64.
// Q,K smem pitch 80B (64B data + 16 pad, conflict-free); Vt pitch 144B.
#define PQ 80
#define PV 144
#define SM_K  (2 * 128 * PQ)          // 20480
#define SM_V  (SM_K + 2 * 64 * PQ)    // 30720
#define SM_AT (SM_V + 2 * 32 * PV)    // 39936 total

__global__ __launch_bounds__(128)
void attn_mma() {
    const int b = blockIdx.z;
    const int h = blockIdx.y;
    const int L = g_len[b];
    const int qt = blockIdx.x * 128;
    if (qt >= L) return;

    __shared__ __align__(16) char sm[SM_AT];
    const uint32_t uQh = smem_u32(sm);
    const uint32_t uKh = uQh + SM_K;
    const uint32_t uVh = uQh + SM_V;

    const int tid = threadIdx.x;
    const int lane = tid & 31;
    const int w = tid >> 5;
    const int wq = w * 32;
    const int g = lane >> 2;
    const int t2 = (lane & 3) * 2;

    // ---- stage Q tile (128 rows x 32 cols = 64B/row, hi+lo) ----
    {
        int r = tid;
        size_t off = ((size_t)(b * S + qt + r)) * E + h * D;
        const uint4* sh = (const uint4*)(g_qhi + off);
        const uint4* sl = (const uint4*)(g_qlo + off);
        #pragma unroll
        for (int j = 0; j < 4; j++) {
            *(uint4*)(sm + r * PQ + 16 * j)            = sh[j];
            *(uint4*)(sm + 128 * PQ + r * PQ + 16 * j) = sl[j];
        }
    }
    __syncthreads();

    // Q fragments (kept in registers for the whole kernel)
    uint32_t qh[2][2][4], ql[2][2][4];
    #pragma unroll
    for (int mi = 0; mi < 2; mi++)
        #pragma unroll
        for (int s = 0; s < 2; s++) {
            uint32_t ad = uQh + (wq + mi * 16 + (lane & 15)) * PQ
                        + (lane >> 4) * 16 + s * 32;
            ldsm4(qh[mi][s], ad);
            ldsm4(ql[mi][s], ad + 128 * PQ);
        }

    float mx[2][2], lsum[2][2], acc[2][4][4];
    #pragma unroll
    for (int mi = 0; mi < 2; mi++)
        #pragma unroll
        for (int hf = 0; hf < 2; hf++) { mx[mi][hf] = -1e30f; lsum[mi][hf] = 0.f; }
    #pragma unroll
    for (int mi = 0; mi < 2; mi++)
        #pragma unroll
        for (int nd = 0; nd < 4; nd++)
            #pragma unroll
            for (int c = 0; c < 4; c++) acc[mi][nd][c] = 0.f;

    for (int k0 = 0; k0 < L; k0 += 64) {
        const int tn = min(64, L - k0);
        __syncthreads();                       // previous tile's reads done

        // ---- stage K tile: 64 rows x 64B (hi or lo per thread-half) ----
        {
            int r = tid & 63;
            size_t off = ((size_t)(b * S + k0 + r)) * E + h * D;
            const uint4* src = (const uint4*)(((tid < 64) ? g_khi : g_klo) + off);
            char* dst = sm + SM_K + ((tid < 64) ? 0 : 64 * PQ) + r * PQ;
            #pragma unroll
            for (int j = 0; j < 4; j++)
                *(uint4*)(dst + 16 * j) = src[j];
        }
        // ---- stage Vt (transpose): thread = (kpair, dchunk) ----
        {
            int kp = tid & 31, dc = tid >> 5;
            size_t base0 = ((size_t)(b * S + k0 + 2 * kp)) * E + h * D + dc * 8;
            uint4 vh0 = *(const uint4*)(g_vhi + base0);
            uint4 vh1 = *(const uint4*)(g_vhi + base0 + E);
            uint4 vl0 = *(const uint4*)(g_vlo + base0);
            uint4 vl1 = *(const uint4*)(g_vlo + base0 + E);
            const uint32_t* h0 = (const uint32_t*)&vh0;
            const uint32_t* h1 = (const uint32_t*)&vh1;
            const uint32_t* l0 = (const uint32_t*)&vl0;
            const uint32_t* l1 = (const uint32_t*)&vl1;
            #pragma unroll
            for (int d = 0; d < 8; d++) {
                uint32_t e0 = (d & 1) ? (h0[d >> 1] >> 16) : (h0[d >> 1] & 0xffff);
                uint32_t e1 = (d & 1) ? (h1[d >> 1] >> 16) : (h1[d >> 1] & 0xffff);
                *(uint32_t*)(sm + SM_V + (dc * 8 + d) * PV + kp * 4) = (e1 << 16) | e0;
                uint32_t f0 = (d & 1) ? (l0[d >> 1] >> 16) : (l0[d >> 1] & 0xffff);
                uint32_t f1 = (d & 1) ? (l1[d >> 1] >> 16) : (l1[d >> 1] & 0xffff);
                *(uint32_t*)(sm + SM_V + 32 * PV + (dc * 8 + d) * PV + kp * 4)
                    = (f1 << 16) | f0;
            }
        }
        __syncthreads();

        // ---- scores: S[32q x 64k] per warp, bf16x3 compensated ----
        float sc[2][8][4];
        #pragma unroll
        for (int mi = 0; mi < 2; mi++)
            #pragma unroll
            for (int nj = 0; nj < 8; nj++)
                #pragma unroll
                for (int c = 0; c < 4; c++) sc[mi][nj][c] = 0.f;

        #pragma unroll
        for (int njp = 0; njp < 4; njp++) {
            uint32_t kh[2][4], kl[2][4];
            #pragma unroll
            for (int s = 0; s < 2; s++) {
                uint32_t ad = uKh + (njp * 16 + (lane & 15)) * PQ
                            + (lane >> 4) * 16 + s * 32;
                ldsm4(kh[s], ad);
                ldsm4(kl[s], ad + 64 * PQ);
            }
            #pragma unroll
            for (int mi = 0; mi < 2; mi++)
                #pragma unroll
                for (int j2 = 0; j2 < 2; j2++) {
                    float* dst = sc[mi][njp * 2 + j2];
                    #pragma unroll
                    for (int s = 0; s < 2; s++) {
                        mma16816(dst, qh[mi][s], kh[s][j2], kh[s][2 + j2]);
                        mma16816(dst, qh[mi][s], kl[s][j2], kl[s][2 + j2]);
                        mma16816(dst, ql[mi][s], kh[s][j2], kh[s][2 + j2]);
                    }
                }
        }

        // ---- mask tail keys ----
        if (tn < 64) {
            #pragma unroll
            for (int mi = 0; mi < 2; mi++)
                #pragma unroll
                for (int nj = 0; nj < 8; nj++)
                    #pragma unroll
                    for (int c = 0; c < 4; c++) {
                        int kc = nj * 8 + t2 + (c & 1);
                        if (kc >= tn) sc[mi][nj][c] = -1e30f;
                    }
        }

        // ---- online softmax (per row; rows g and g+8 of each m-tile) ----
        #pragma unroll
        for (int mi = 0; mi < 2; mi++)
            #pragma unroll
            for (int hf = 0; hf < 2; hf++) {
                float vmax = -1e30f;
                #pragma unroll
                for (int nj = 0; nj < 8; nj++) {
                    vmax = fmaxf(vmax, sc[mi][nj][hf * 2]);
                    vmax = fmaxf(vmax, sc[mi][nj][hf * 2 + 1]);
                }
                vmax = fmaxf(vmax, __shfl_xor_sync(0xffffffffu, vmax, 1));
                vmax = fmaxf(vmax, __shfl_xor_sync(0xffffffffu, vmax, 2));
                float mold = mx[mi][hf];
                float mnew = fmaxf(mold, vmax);
                mx[mi][hf] = mnew;
                float rs = ex2(mold - mnew);
                lsum[mi][hf] *= rs;
                #pragma unroll
                for (int nd = 0; nd < 4; nd++) {
                    acc[mi][nd][hf * 2] *= rs;
                    acc[mi][nd][hf * 2 + 1] *= rs;
                }
                float rowsum = 0.f;
                #pragma unroll
                for (int nj = 0; nj < 8; nj++) {
                    float p0 = ex2(sc[mi][nj][hf * 2] - mnew);
                    float p1 = ex2(sc[mi][nj][hf * 2 + 1] - mnew);
                    sc[mi][nj][hf * 2] = p0;
                    sc[mi][nj][hf * 2 + 1] = p1;
                    rowsum += p0 + p1;
                }
                rowsum += __shfl_xor_sync(0xffffffffu, rowsum, 1);
                rowsum += __shfl_xor_sync(0xffffffffu, rowsum, 2);
                lsum[mi][hf] += rowsum;
            }

        // ---- PV: O += P * V, bf16x3 compensated ----
        #pragma unroll
        for (int sp = 0; sp < 2; sp++) {
            uint32_t ph[2][2][4], pl[2][2][4];
            #pragma unroll
            for (int mi = 0; mi < 2; mi++)
                #pragma unroll
                for (int ss = 0; ss < 2; ss++) {
                    int s = sp * 2 + ss;
                    float* c0 = sc[mi][2 * s];
                    float* c1 = sc[mi][2 * s + 1];
                    split_pair(c0[0], c0[1], ph[mi][ss][0], pl[mi][ss][0]);
                    split_pair(c0[2], c0[3], ph[mi][ss][1], pl[mi][ss][1]);
                    split_pair(c1[0], c1[1], ph[mi][ss][2], pl[mi][ss][2]);
                    split_pair(c1[2], c1[3], ph[mi][ss][3], pl[mi][ss][3]);
                }
            #pragma unroll
            for (int nd = 0; nd < 4; nd++) {
                uint32_t vh[4], vl[4];
                uint32_t ad = uVh + (nd * 8 + (lane & 7)) * PV
                            + sp * 64 + (lane >> 3) * 16;
                ldsm4(vh, ad);
                ldsm4(vl, ad + 32 * PV);
                #pragma unroll
                for (int mi = 0; mi < 2; mi++)
                    #pragma unroll
                    for (int ss = 0; ss < 2; ss++) {
                        mma16816(acc[mi][nd], ph[mi][ss], vh[ss*2], vh[ss*2+1]);
                        mma16816(acc[mi][nd], pl[mi][ss], vh[ss*2], vh[ss*2+1]);
                        mma16816(acc[mi][nd], ph[mi][ss], vl[ss*2], vl[ss*2+1]);
                    }
            }
        }
    }

    // ---- epilogue: O/l, hi/lo split, scrambled-layout write ----
    #pragma unroll
    for (int mi = 0; mi < 2; mi++)
        #pragma unroll
        for (int hf = 0; hf < 2; hf++) {
            int q = qt + wq + mi * 16 + g + hf * 8;
            if (q < L) {
                float inv = 1.f / lsum[mi][hf];
                #pragma unroll
                for (int nd = 0; nd < 4; nd++) {
                    float o0 = acc[mi][nd][hf * 2] * inv;
                    float o1 = acc[mi][nd][hf * 2 + 1] * inv;
                    uint32_t hh, ll;
                    split_pair(o0, o1, hh, ll);
                    size_t off = (size_t)b * S * E + ((size_t)h * L + q) * D
                               + nd * 8 + t2;
                    *(uint32_t*)(g_phi + off) = hh;
                    *(uint32_t*)(g_plo + off) = ll;
                }
            }
        }
}

// ---------------- launch ------------------------------------------------------
extern "C" void kernel_launch(void* const* d_in, const int* in_sizes, int n_in,
                              void* d_out, int out_size) {
    const float* x    = (const float*)d_in[0];
    const int*   mask = (const int*)  d_in[1];
    const float* Wq   = (const float*)d_in[2];
    const float* Wk   = (const float*)d_in[3];
    const float* Wv   = (const float*)d_in[4];
    const float* Wo   = (const float*)d_in[5];
    float* out = (float*)d_out;

    __nv_bfloat16 *xhi, *xlo, *qhi, *qlo, *khi, *klo, *vhi, *vlo, *phi, *plo, *whi, *wlo;
    cudaGetSymbolAddress((void**)&xhi, g_xhi);
    cudaGetSymbolAddress((void**)&xlo, g_xlo);
    cudaGetSymbolAddress((void**)&qhi, g_qhi);
    cudaGetSymbolAddress((void**)&qlo, g_qlo);
    cudaGetSymbolAddress((void**)&khi, g_khi);
    cudaGetSymbolAddress((void**)&klo, g_klo);
    cudaGetSymbolAddress((void**)&vhi, g_vhi);
    cudaGetSymbolAddress((void**)&vlo, g_vlo);
    cudaGetSymbolAddress((void**)&phi, g_phi);
    cudaGetSymbolAddress((void**)&plo, g_plo);
    cudaGetSymbolAddress((void**)&whi, g_whi);
    cudaGetSymbolAddress((void**)&wlo, g_wlo);

    cudaFuncSetAttribute(gemm_mma, cudaFuncAttributeMaxDynamicSharedMemorySize,
                         GEMM_SMEM);

    len_kernel<<<B, 256>>>(mask);
    cudaMemsetAsync(phi, 0, (size_t)M * E * sizeof(__nv_bfloat16), 0);
    cudaMemsetAsync(plo, 0, (size_t)M * E * sizeof(__nv_bfloat16), 0);

    decomp_kernel<<<(M*E/4 + 255)/256, 256>>>(x, xhi, xlo, M*E/4);
    decompw_kernel<<<dim3(E*E/4/256, 4), 256>>>(Wq, Wk, Wv, Wo, whi, wlo);

    dim3 gg(M / 128, E / 128);
    gemm_mma<<<gg, 512, GEMM_SMEM>>>(xhi, xlo, whi + 0*E*E, wlo + 0*E*E,
                                     nullptr, qhi, qlo);
    gemm_mma<<<gg, 512, GEMM_SMEM>>>(xhi, xlo, whi + 1*E*E, wlo + 1*E*E,
                                     nullptr, khi, klo);
    gemm_mma<<<gg, 512, GEMM_SMEM>>>(xhi, xlo, whi + 2*E*E, wlo + 2*E*E,
                                     nullptr, vhi, vlo);

    dim3 ga(S / 128, H, B);
    attn_mma<<<ga, 128>>>();

    gemm_mma<<<gg, 512, GEMM_SMEM>>>(phi, plo, whi + 3*E*E, wlo + 3*E*E,
                                     out, nullptr, nullptr);
}

// round 6
// speedup vs baseline: 3.5783x; 1.0090x over previous
#include <cuda_runtime.h>
#include <cuda_bf16.h>
#include <stdint.h>

#define B 4
#define S 2048
#define E 256
#define H 8
#define D 32
#define M (B*S)
// SCALE * log2(e), folded into Wq at decomposition time
#define CEXP (0.17677669529663687f * 1.44269504088896341f)

// ---------------- scratch (device globals; no allocation allowed) ----------
static __device__ __align__(16) __nv_bfloat16 g_xhi[M*E];
static __device__ __align__(16) __nv_bfloat16 g_xlo[M*E];
static __device__ __align__(16) __nv_bfloat16 g_qhi[M*E];
static __device__ __align__(16) __nv_bfloat16 g_qlo[M*E];
static __device__ __align__(16) __nv_bfloat16 g_khi[M*E];
static __device__ __align__(16) __nv_bfloat16 g_klo[M*E];
static __device__ __align__(16) __nv_bfloat16 g_vhi[M*E];
static __device__ __align__(16) __nv_bfloat16 g_vlo[M*E];
static __device__ __align__(16) __nv_bfloat16 g_phi[M*E];
static __device__ __align__(16) __nv_bfloat16 g_plo[M*E];
static __device__ __align__(16) __nv_bfloat16 g_whi[4*E*E];
static __device__ __align__(16) __nv_bfloat16 g_wlo[4*E*E];
static __device__ int g_len[B];

// ---------------- helpers ----------------------------------------------------
__device__ __forceinline__ uint32_t smem_u32(const void* p) {
    uint32_t a;
    asm("{ .reg .u64 t; cvta.to.shared.u64 t, %1; cvt.u32.u64 %0, t; }"
        : "=r"(a) : "l"(p));
    return a;
}

__device__ __forceinline__ void ldsm4(uint32_t* r, uint32_t addr) {
    asm volatile("ldmatrix.sync.aligned.m8n8.x4.shared.b16 {%0,%1,%2,%3}, [%4];"
                 : "=r"(r[0]), "=r"(r[1]), "=r"(r[2]), "=r"(r[3]) : "r"(addr));
}

__device__ __forceinline__ void mma16816(float* d, const uint32_t* a,
                                         uint32_t b0, uint32_t b1) {
    asm volatile(
        "mma.sync.aligned.m16n8k16.row.col.f32.bf16.bf16.f32 "
        "{%0,%1,%2,%3}, {%4,%5,%6,%7}, {%8,%9}, {%0,%1,%2,%3};"
        : "+f"(d[0]), "+f"(d[1]), "+f"(d[2]), "+f"(d[3])
        : "r"(a[0]), "r"(a[1]), "r"(a[2]), "r"(a[3]), "r"(b0), "r"(b1));
}

__device__ __forceinline__ float ex2(float x) {
    float y;
    asm("ex2.approx.ftz.f32 %0, %1;" : "=f"(y) : "f"(x));
    return y;
}

// pack (a -> low, b -> high) as bf16x2, plus residual lo pair
__device__ __forceinline__ void split_pair(float a, float b,
                                           uint32_t& hi, uint32_t& lo) {
    uint32_t h;
    asm("cvt.rn.bf16x2.f32 %0, %1, %2;" : "=r"(h) : "f"(b), "f"(a));
    float ha = __uint_as_float(h << 16);
    float hb = __uint_as_float(h & 0xffff0000u);
    uint32_t l;
    asm("cvt.rn.bf16x2.f32 %0, %1, %2;" : "=r"(l) : "f"(b - hb), "f"(a - ha));
    hi = h;
    lo = l;
}

// ---------------- lengths ----------------------------------------------------
__global__ void len_kernel(const int* __restrict__ mask) {
    int b = blockIdx.x;
    int t = threadIdx.x;
    int s = 0;
    for (int i = t; i < S; i += 256) s += mask[b*S + i];
    __shared__ int sh[256];
    sh[t] = s;
    __syncthreads();
    for (int o = 128; o > 0; o >>= 1) {
        if (t < o) sh[t] += sh[t + o];
        __syncthreads();
    }
    if (t == 0) g_len[b] = sh[0];
}

// ---------------- fp32 -> bf16 hi/lo decomposition ---------------------------
__global__ __launch_bounds__(256)
void decomp_kernel(const float* __restrict__ x, __nv_bfloat16* __restrict__ hi,
                   __nv_bfloat16* __restrict__ lo, int n4) {
    int i = blockIdx.x * 256 + threadIdx.x;
    if (i >= n4) return;
    float4 v = ((const float4*)x)[i];
    float f[4] = {v.x, v.y, v.z, v.w};
    #pragma unroll
    for (int j = 0; j < 4; j++) {
        __nv_bfloat16 h = __float2bfloat16(f[j]);
        hi[4*i + j] = h;
        lo[4*i + j] = __float2bfloat16(f[j] - __bfloat162float(h));
    }
}

// all 4 weight matrices in one launch; Wq (y==0) pre-scaled by CEXP
__global__ __launch_bounds__(256)
void decompw_kernel(const float* __restrict__ w0, const float* __restrict__ w1,
                    const float* __restrict__ w2, const float* __restrict__ w3,
                    __nv_bfloat16* __restrict__ hi, __nv_bfloat16* __restrict__ lo) {
    int m = blockIdx.y;
    const float* src = (m == 0) ? w0 : (m == 1) ? w1 : (m == 2) ? w2 : w3;
    float sc = (m == 0) ? CEXP : 1.0f;
    int i = blockIdx.x * 256 + threadIdx.x;           // over E*E/4
    float4 v = ((const float4*)src)[i];
    float f[4] = {v.x * sc, v.y * sc, v.z * sc, v.w * sc};
    size_t base = (size_t)m * E * E + 4 * (size_t)i;
    #pragma unroll
    for (int j = 0; j < 4; j++) {
        __nv_bfloat16 h = __float2bfloat16(f[j]);
        hi[base + j] = h;
        lo[base + j] = __float2bfloat16(f[j] - __bfloat162float(h));
    }
}

// ---------------- mma.sync bf16x3 GEMM core ----------------------------------
// CTA 128x128, 512 threads, warp tile 32x32, K chunks of 64 double-buffered.
#define GPITCH 144
#define GCHUNKB (128 * GPITCH)
#define GBUFB (4 * GCHUNKB)
#define GEMM_SMEM (2 * GBUFB)                 // 147456

__device__ __forceinline__ void gemm_core(
    const __nv_bfloat16* __restrict__ Ahi, const __nv_bfloat16* __restrict__ Alo,
    const __nv_bfloat16* __restrict__ Bhi, const __nv_bfloat16* __restrict__ Blo,
    float* __restrict__ Yf,
    __nv_bfloat16* __restrict__ Yhi, __nv_bfloat16* __restrict__ Ylo,
    char* smem) {
    const int bm = blockIdx.x * 128;
    const int bn = blockIdx.y * 128;
    const int tid = threadIdx.x;
    const int lane = tid & 31;
    const int wid = tid >> 5;
    const int wm = (wid & 3) * 32;
    const int wn = (wid >> 2) * 32;
    const uint32_t base = smem_u32(smem);

    float acc[2][4][4];
    #pragma unroll
    for (int mi = 0; mi < 2; mi++)
        #pragma unroll
        for (int ni = 0; ni < 4; ni++)
            #pragma unroll
            for (int k = 0; k < 4; k++) acc[mi][ni][k] = 0.f;

    const int a_row = lane & 15;
    const int a_kb  = (lane >> 4) * 16;
    const int pr0 = tid >> 3, pc0 = tid & 7;            // prefetch row/col (i=0)
    const int pr1 = (tid + 512) >> 3, pc1 = (tid + 512) & 7;

    float4 pf[8];
    #define PFLOAD(k0) do { \
        size_t g0 = (size_t)pr0 * E + (k0) + pc0 * 8; \
        size_t g1 = (size_t)pr1 * E + (k0) + pc1 * 8; \
        pf[0] = *(const float4*)(Ahi + (size_t)bm * E + g0); \
        pf[1] = *(const float4*)(Alo + (size_t)bm * E + g0); \
        pf[2] = *(const float4*)(Bhi + (size_t)bn * E + g0); \
        pf[3] = *(const float4*)(Blo + (size_t)bn * E + g0); \
        pf[4] = *(const float4*)(Ahi + (size_t)bm * E + g1); \
        pf[5] = *(const float4*)(Alo + (size_t)bm * E + g1); \
        pf[6] = *(const float4*)(Bhi + (size_t)bn * E + g1); \
        pf[7] = *(const float4*)(Blo + (size_t)bn * E + g1); \
    } while (0)
    #define PFSTORE(buf) do { \
        char* bp = smem + (buf) * GBUFB; \
        int s0 = pr0 * GPITCH + pc0 * 16; \
        int s1 = pr1 * GPITCH + pc1 * 16; \
        *(float4*)(bp + s0)               = pf[0]; \
        *(float4*)(bp + GCHUNKB + s0)     = pf[1]; \
        *(float4*)(bp + 2 * GCHUNKB + s0) = pf[2]; \
        *(float4*)(bp + 3 * GCHUNKB + s0) = pf[3]; \
        *(float4*)(bp + s1)               = pf[4]; \
        *(float4*)(bp + GCHUNKB + s1)     = pf[5]; \
        *(float4*)(bp + 2 * GCHUNKB + s1) = pf[6]; \
        *(float4*)(bp + 3 * GCHUNKB + s1) = pf[7]; \
    } while (0)

    PFLOAD(0);
    PFSTORE(0);
    __syncthreads();

    for (int kc = 0; kc < 4; kc++) {
        if (kc < 3) PFLOAD((kc + 1) * 64);
        const uint32_t uA = base + (kc & 1) * GBUFB;
        const uint32_t uB = uA + 2 * GCHUNKB;

        #pragma unroll
        for (int ks = 0; ks < 4; ks++) {
            const int kb = ks * 32;
            uint32_t ahi[2][4], alo[2][4], bhi[4][2], blo[4][2];
            #pragma unroll
            for (int mi = 0; mi < 2; mi++) {
                uint32_t off = (uint32_t)((wm + mi * 16 + a_row) * GPITCH + kb + a_kb);
                ldsm4(ahi[mi], uA + off);
                ldsm4(alo[mi], uA + GCHUNKB + off);
            }
            #pragma unroll
            for (int np = 0; np < 2; np++) {
                uint32_t off = (uint32_t)((wn + np * 16 + a_row) * GPITCH + kb + a_kb);
                uint32_t th[4], tl[4];
                ldsm4(th, uB + off);
                ldsm4(tl, uB + GCHUNKB + off);
                bhi[np*2][0] = th[0]; bhi[np*2][1] = th[2];
                bhi[np*2+1][0] = th[1]; bhi[np*2+1][1] = th[3];
                blo[np*2][0] = tl[0]; blo[np*2][1] = tl[2];
                blo[np*2+1][0] = tl[1]; blo[np*2+1][1] = tl[3];
            }
            #pragma unroll
            for (int mi = 0; mi < 2; mi++)
                #pragma unroll
                for (int ni = 0; ni < 4; ni++) {
                    mma16816(acc[mi][ni], ahi[mi], bhi[ni][0], bhi[ni][1]);
                    mma16816(acc[mi][ni], ahi[mi], blo[ni][0], blo[ni][1]);
                    mma16816(acc[mi][ni], alo[mi], bhi[ni][0], bhi[ni][1]);
                }
        }
        if (kc < 3) {
            PFSTORE((kc + 1) & 1);
            __syncthreads();
        }
    }

    const int g = lane >> 2;
    const int t2 = (lane & 3) * 2;
    #pragma unroll
    for (int mi = 0; mi < 2; mi++)
        #pragma unroll
        for (int ni = 0; ni < 4; ni++) {
            int row = bm + wm + mi * 16 + g;
            int col = bn + wn + ni * 8 + t2;
            if (Yf) {
                *(float2*)&Yf[(size_t)row * E + col] =
                    make_float2(acc[mi][ni][0], acc[mi][ni][1]);
                *(float2*)&Yf[(size_t)(row + 8) * E + col] =
                    make_float2(acc[mi][ni][2], acc[mi][ni][3]);
            } else {
                uint32_t h0, l0, h1, l1;
                split_pair(acc[mi][ni][0], acc[mi][ni][1], h0, l0);
                split_pair(acc[mi][ni][2], acc[mi][ni][3], h1, l1);
                *(uint32_t*)(Yhi + (size_t)row * E + col) = h0;
                *(uint32_t*)(Ylo + (size_t)row * E + col) = l0;
                *(uint32_t*)(Yhi + (size_t)(row + 8) * E + col) = h1;
                *(uint32_t*)(Ylo + (size_t)(row + 8) * E + col) = l1;
            }
        }
    #undef PFLOAD
    #undef PFSTORE
}

struct QKVOuts {
    __nv_bfloat16 *h0, *l0, *h1, *l1, *h2, *l2;
};

// fused Q/K/V projections: grid.z selects weight + destination
__global__ __launch_bounds__(512, 1)
void gemm_qkv(const __nv_bfloat16* __restrict__ xhi, const __nv_bfloat16* __restrict__ xlo,
              const __nv_bfloat16* __restrict__ whi, const __nv_bfloat16* __restrict__ wlo,
              QKVOuts o) {
    extern __shared__ char smem[];
    const int z = blockIdx.z;
    const __nv_bfloat16* Bh = whi + (size_t)z * E * E;
    const __nv_bfloat16* Bl = wlo + (size_t)z * E * E;
    __nv_bfloat16* Yh = (z == 0) ? o.h0 : (z == 1) ? o.h1 : o.h2;
    __nv_bfloat16* Yl = (z == 0) ? o.l0 : (z == 1) ? o.l1 : o.l2;
    gemm_core(xhi, xlo, Bh, Bl, nullptr, Yh, Yl, smem);
}

__global__ __launch_bounds__(512, 1)
void gemm_out(const __nv_bfloat16* __restrict__ phi, const __nv_bfloat16* __restrict__ plo,
              const __nv_bfloat16* __restrict__ whi, const __nv_bfloat16* __restrict__ wlo,
              float* __restrict__ Yf) {
    extern __shared__ char smem[];
    gemm_core(phi, plo, whi, wlo, Yf, nullptr, nullptr, smem);
}

// ---------------- tensor-core varlen flash attention --------------------------
// CTA: 256 queries of one (b,h); 8 warps x 32 q-rows; key tiles of 64.
// Q,K smem pitch 80B (64B data + 16 pad); Vt pitch 144B. Dynamic smem.
#define PQ 80
#define PV 144
#define SM_K  (2 * 256 * PQ)          // 40960
#define SM_V  (SM_K + 2 * 64 * PQ)    // 51200
#define ATTN_SMEM (SM_V + 2 * 32 * PV) // 60416

__global__ __launch_bounds__(256)
void attn_mma() {
    const int b = blockIdx.z;
    const int h = blockIdx.y;
    const int L = g_len[b];
    const int qt = blockIdx.x * 256;
    if (qt >= L) return;

    extern __shared__ char sm[];
    const uint32_t uQh = smem_u32(sm);
    const uint32_t uKh = uQh + SM_K;
    const uint32_t uVh = uQh + SM_V;

    const int tid = threadIdx.x;
    const int lane = tid & 31;
    const int w = tid >> 5;
    const int wq = w * 32;
    const int g = lane >> 2;
    const int t2 = (lane & 3) * 2;

    // ---- stage Q tile (256 rows x 32 cols = 64B/row, hi+lo) ----
    {
        int r = tid;
        size_t off = ((size_t)(b * S + qt + r)) * E + h * D;
        const uint4* sh = (const uint4*)(g_qhi + off);
        const uint4* sl = (const uint4*)(g_qlo + off);
        #pragma unroll
        for (int j = 0; j < 4; j++) {
            *(uint4*)(sm + r * PQ + 16 * j)            = sh[j];
            *(uint4*)(sm + 256 * PQ + r * PQ + 16 * j) = sl[j];
        }
    }
    __syncthreads();

    // Q fragments (kept in registers for the whole kernel)
    uint32_t qh[2][2][4], ql[2][2][4];
    #pragma unroll
    for (int mi = 0; mi < 2; mi++)
        #pragma unroll
        for (int s = 0; s < 2; s++) {
            uint32_t ad = uQh + (wq + mi * 16 + (lane & 15)) * PQ
                        + (lane >> 4) * 16 + s * 32;
            ldsm4(qh[mi][s], ad);
            ldsm4(ql[mi][s], ad + 256 * PQ);
        }

    float mx[2][2], lsum[2][2], acc[2][4][4];
    #pragma unroll
    for (int mi = 0; mi < 2; mi++)
        #pragma unroll
        for (int hf = 0; hf < 2; hf++) { mx[mi][hf] = -1e30f; lsum[mi][hf] = 0.f; }
    #pragma unroll
    for (int mi = 0; mi < 2; mi++)
        #pragma unroll
        for (int nd = 0; nd < 4; nd++)
            #pragma unroll
            for (int c = 0; c < 4; c++) acc[mi][nd][c] = 0.f;

    for (int k0 = 0; k0 < L; k0 += 64) {
        const int tn = min(64, L - k0);
        __syncthreads();                       // previous tile's reads done

        if (tid < 128) {
            // ---- stage Vt (transpose): thread = (kpair, dchunk) ----
            int kp = tid & 31, dc = tid >> 5;  // dc in 0..3
            size_t base0 = ((size_t)(b * S + k0 + 2 * kp)) * E + h * D + dc * 8;
            uint4 vh0 = *(const uint4*)(g_vhi + base0);
            uint4 vh1 = *(const uint4*)(g_vhi + base0 + E);
            uint4 vl0 = *(const uint4*)(g_vlo + base0);
            uint4 vl1 = *(const uint4*)(g_vlo + base0 + E);
            const uint32_t* h0 = (const uint32_t*)&vh0;
            const uint32_t* h1 = (const uint32_t*)&vh1;
            const uint32_t* l0 = (const uint32_t*)&vl0;
            const uint32_t* l1 = (const uint32_t*)&vl1;
            #pragma unroll
            for (int d = 0; d < 8; d++) {
                uint32_t e0 = (d & 1) ? (h0[d >> 1] >> 16) : (h0[d >> 1] & 0xffff);
                uint32_t e1 = (d & 1) ? (h1[d >> 1] >> 16) : (h1[d >> 1] & 0xffff);
                *(uint32_t*)(sm + SM_V + (dc * 8 + d) * PV + kp * 4) = (e1 << 16) | e0;
                uint32_t f0 = (d & 1) ? (l0[d >> 1] >> 16) : (l0[d >> 1] & 0xffff);
                uint32_t f1 = (d & 1) ? (l1[d >> 1] >> 16) : (l1[d >> 1] & 0xffff);
                *(uint32_t*)(sm + SM_V + 32 * PV + (dc * 8 + d) * PV + kp * 4)
                    = (f1 << 16) | f0;
            }
        } else {
            // ---- stage K tile: 64 rows x 64B, hi (arr=0) and lo (arr=1) ----
            int u = tid - 128;
            int arr = u >> 6, r = u & 63;
            size_t off = ((size_t)(b * S + k0 + r)) * E + h * D;
            const uint4* src = (const uint4*)((arr ? g_klo : g_khi) + off);
            char* dst = sm + SM_K + arr * 64 * PQ + r * PQ;
            #pragma unroll
            for (int j = 0; j < 4; j++)
                *(uint4*)(dst + 16 * j) = src[j];
        }
        __syncthreads();

        // ---- scores: S[32q x 64k] per warp, bf16x3 compensated ----
        float sc[2][8][4];
        #pragma unroll
        for (int mi = 0; mi < 2; mi++)
            #pragma unroll
            for (int nj = 0; nj < 8; nj++)
                #pragma unroll
                for (int c = 0; c < 4; c++) sc[mi][nj][c] = 0.f;

        #pragma unroll
        for (int njp = 0; njp < 4; njp++) {
            uint32_t kh[2][4], kl[2][4];
            #pragma unroll
            for (int s = 0; s < 2; s++) {
                uint32_t ad = uKh + (njp * 16 + (lane & 15)) * PQ
                            + (lane >> 4) * 16 + s * 32;
                ldsm4(kh[s], ad);
                ldsm4(kl[s], ad + 64 * PQ);
            }
            #pragma unroll
            for (int mi = 0; mi < 2; mi++)
                #pragma unroll
                for (int j2 = 0; j2 < 2; j2++) {
                    float* dst = sc[mi][njp * 2 + j2];
                    #pragma unroll
                    for (int s = 0; s < 2; s++) {
                        mma16816(dst, qh[mi][s], kh[s][j2], kh[s][2 + j2]);
                        mma16816(dst, qh[mi][s], kl[s][j2], kl[s][2 + j2]);
                        mma16816(dst, ql[mi][s], kh[s][j2], kh[s][2 + j2]);
                    }
                }
        }

        // ---- mask tail keys ----
        if (tn < 64) {
            #pragma unroll
            for (int mi = 0; mi < 2; mi++)
                #pragma unroll
                for (int nj = 0; nj < 8; nj++)
                    #pragma unroll
                    for (int c = 0; c < 4; c++) {
                        int kc = nj * 8 + t2 + (c & 1);
                        if (kc >= tn) sc[mi][nj][c] = -1e30f;
                    }
        }

        // ---- online softmax (per row; rows g and g+8 of each m-tile) ----
        #pragma unroll
        for (int mi = 0; mi < 2; mi++)
            #pragma unroll
            for (int hf = 0; hf < 2; hf++) {
                float vmax = -1e30f;
                #pragma unroll
                for (int nj = 0; nj < 8; nj++) {
                    vmax = fmaxf(vmax, sc[mi][nj][hf * 2]);
                    vmax = fmaxf(vmax, sc[mi][nj][hf * 2 + 1]);
                }
                vmax = fmaxf(vmax, __shfl_xor_sync(0xffffffffu, vmax, 1));
                vmax = fmaxf(vmax, __shfl_xor_sync(0xffffffffu, vmax, 2));
                float mold = mx[mi][hf];
                float mnew = fmaxf(mold, vmax);
                mx[mi][hf] = mnew;
                float rs = ex2(mold - mnew);
                lsum[mi][hf] *= rs;
                #pragma unroll
                for (int nd = 0; nd < 4; nd++) {
                    acc[mi][nd][hf * 2] *= rs;
                    acc[mi][nd][hf * 2 + 1] *= rs;
                }
                float rowsum = 0.f;
                #pragma unroll
                for (int nj = 0; nj < 8; nj++) {
                    float p0 = ex2(sc[mi][nj][hf * 2] - mnew);
                    float p1 = ex2(sc[mi][nj][hf * 2 + 1] - mnew);
                    sc[mi][nj][hf * 2] = p0;
                    sc[mi][nj][hf * 2 + 1] = p1;
                    rowsum += p0 + p1;
                }
                rowsum += __shfl_xor_sync(0xffffffffu, rowsum, 1);
                rowsum += __shfl_xor_sync(0xffffffffu, rowsum, 2);
                lsum[mi][hf] += rowsum;
            }

        // ---- PV: O += P * V, bf16x3 compensated ----
        #pragma unroll
        for (int sp = 0; sp < 2; sp++) {
            uint32_t ph[2][2][4], pl[2][2][4];
            #pragma unroll
            for (int mi = 0; mi < 2; mi++)
                #pragma unroll
                for (int ss = 0; ss < 2; ss++) {
                    int s = sp * 2 + ss;
                    float* c0 = sc[mi][2 * s];
                    float* c1 = sc[mi][2 * s + 1];
                    split_pair(c0[0], c0[1], ph[mi][ss][0], pl[mi][ss][0]);
                    split_pair(c0[2], c0[3], ph[mi][ss][1], pl[mi][ss][1]);
                    split_pair(c1[0], c1[1], ph[mi][ss][2], pl[mi][ss][2]);
                    split_pair(c1[2], c1[3], ph[mi][ss][3], pl[mi][ss][3]);
                }
            #pragma unroll
            for (int nd = 0; nd < 4; nd++) {
                uint32_t vh[4], vl[4];
                uint32_t ad = uVh + (nd * 8 + (lane & 7)) * PV
                            + sp * 64 + (lane >> 3) * 16;
                ldsm4(vh, ad);
                ldsm4(vl, ad + 32 * PV);
                #pragma unroll
                for (int mi = 0; mi < 2; mi++)
                    #pragma unroll
                    for (int ss = 0; ss < 2; ss++) {
                        mma16816(acc[mi][nd], ph[mi][ss], vh[ss*2], vh[ss*2+1]);
                        mma16816(acc[mi][nd], pl[mi][ss], vh[ss*2], vh[ss*2+1]);
                        mma16816(acc[mi][nd], ph[mi][ss], vl[ss*2], vl[ss*2+1]);
                    }
            }
        }
    }

    // ---- epilogue: O/l, hi/lo split, scrambled-layout write ----
    #pragma unroll
    for (int mi = 0; mi < 2; mi++)
        #pragma unroll
        for (int hf = 0; hf < 2; hf++) {
            int q = qt + wq + mi * 16 + g + hf * 8;
            if (q < L) {
                float inv = 1.f / lsum[mi][hf];
                #pragma unroll
                for (int nd = 0; nd < 4; nd++) {
                    float o0 = acc[mi][nd][hf * 2] * inv;
                    float o1 = acc[mi][nd][hf * 2 + 1] * inv;
                    uint32_t hh, ll;
                    split_pair(o0, o1, hh, ll);
                    size_t off = (size_t)b * S * E + ((size_t)h * L + q) * D
                               + nd * 8 + t2;
                    *(uint32_t*)(g_phi + off) = hh;
                    *(uint32_t*)(g_plo + off) = ll;
                }
            }
        }
}

// ---------------- launch ------------------------------------------------------
extern "C" void kernel_launch(void* const* d_in, const int* in_sizes, int n_in,
                              void* d_out, int out_size) {
    const float* x    = (const float*)d_in[0];
    const int*   mask = (const int*)  d_in[1];
    const float* Wq   = (const float*)d_in[2];
    const float* Wk   = (const float*)d_in[3];
    const float* Wv   = (const float*)d_in[4];
    const float* Wo   = (const float*)d_in[5];
    float* out = (float*)d_out;

    __nv_bfloat16 *xhi, *xlo, *qhi, *qlo, *khi, *klo, *vhi, *vlo, *phi, *plo, *whi, *wlo;
    cudaGetSymbolAddress((void**)&xhi, g_xhi);
    cudaGetSymbolAddress((void**)&xlo, g_xlo);
    cudaGetSymbolAddress((void**)&qhi, g_qhi);
    cudaGetSymbolAddress((void**)&qlo, g_qlo);
    cudaGetSymbolAddress((void**)&khi, g_khi);
    cudaGetSymbolAddress((void**)&klo, g_klo);
    cudaGetSymbolAddress((void**)&vhi, g_vhi);
    cudaGetSymbolAddress((void**)&vlo, g_vlo);
    cudaGetSymbolAddress((void**)&phi, g_phi);
    cudaGetSymbolAddress((void**)&plo, g_plo);
    cudaGetSymbolAddress((void**)&whi, g_whi);
    cudaGetSymbolAddress((void**)&wlo, g_wlo);

    cudaFuncSetAttribute(gemm_qkv, cudaFuncAttributeMaxDynamicSharedMemorySize,
                         GEMM_SMEM);
    cudaFuncSetAttribute(gemm_out, cudaFuncAttributeMaxDynamicSharedMemorySize,
                         GEMM_SMEM);
    cudaFuncSetAttribute(attn_mma, cudaFuncAttributeMaxDynamicSharedMemorySize,
                         ATTN_SMEM);

    len_kernel<<<B, 256>>>(mask);
    cudaMemsetAsync(phi, 0, (size_t)M * E * sizeof(__nv_bfloat16), 0);
    cudaMemsetAsync(plo, 0, (size_t)M * E * sizeof(__nv_bfloat16), 0);

    decomp_kernel<<<(M*E/4 + 255)/256, 256>>>(x, xhi, xlo, M*E/4);
    decompw_kernel<<<dim3(E*E/4/256, 4), 256>>>(Wq, Wk, Wv, Wo, whi, wlo);

    QKVOuts o = { qhi, qlo, khi, klo, vhi, vlo };
    dim3 gq(M / 128, E / 128, 3);
    gemm_qkv<<<gq, 512, GEMM_SMEM>>>(xhi, xlo, whi, wlo, o);

    dim3 ga(S / 256, H, B);
    attn_mma<<<ga, 256, ATTN_SMEM>>>();

    dim3 gg(M / 128, E / 128);
    gemm_out<<<gg, 512, GEMM_SMEM>>>(phi, plo, whi + 3*E*E, wlo + 3*E*E, out);
}

// round 7
// speedup vs baseline: 4.1592x; 1.1623x over previous
#include <cuda_runtime.h>
#include <cuda_bf16.h>
#include <stdint.h>

#define B 4
#define S 2048
#define E 256
#define H 8
#define D 32
#define M (B*S)
// SCALE * log2(e), folded into Wq at decomposition time
#define CEXP (0.17677669529663687f * 1.44269504088896341f)

// ---------------- scratch (device globals; no allocation allowed) ----------
static __device__ __align__(16) __nv_bfloat16 g_xhi[M*E];
static __device__ __align__(16) __nv_bfloat16 g_xlo[M*E];
static __device__ __align__(16) __nv_bfloat16 g_qhi[M*E];
static __device__ __align__(16) __nv_bfloat16 g_qlo[M*E];
static __device__ __align__(16) __nv_bfloat16 g_khi[M*E];
static __device__ __align__(16) __nv_bfloat16 g_klo[M*E];
static __device__ __align__(16) __nv_bfloat16 g_vhi[M*E];
static __device__ __align__(16) __nv_bfloat16 g_vlo[M*E];
static __device__ __align__(16) __nv_bfloat16 g_phi[M*E];
static __device__ __align__(16) __nv_bfloat16 g_plo[M*E];
static __device__ __align__(16) __nv_bfloat16 g_whi[4*E*E];
static __device__ __align__(16) __nv_bfloat16 g_wlo[4*E*E];
static __device__ int g_len[B];

// ---------------- helpers ----------------------------------------------------
__device__ __forceinline__ uint32_t smem_u32(const void* p) {
    uint32_t a;
    asm("{ .reg .u64 t; cvta.to.shared.u64 t, %1; cvt.u32.u64 %0, t; }"
        : "=r"(a) : "l"(p));
    return a;
}

__device__ __forceinline__ void ldsm4(uint32_t* r, uint32_t addr) {
    asm volatile("ldmatrix.sync.aligned.m8n8.x4.shared.b16 {%0,%1,%2,%3}, [%4];"
                 : "=r"(r[0]), "=r"(r[1]), "=r"(r[2]), "=r"(r[3]) : "r"(addr));
}

__device__ __forceinline__ void ldsm4t(uint32_t* r, uint32_t addr) {
    asm volatile("ldmatrix.sync.aligned.m8n8.x4.trans.shared.b16 {%0,%1,%2,%3}, [%4];"
                 : "=r"(r[0]), "=r"(r[1]), "=r"(r[2]), "=r"(r[3]) : "r"(addr));
}

__device__ __forceinline__ void mma16816(float* d, const uint32_t* a,
                                         uint32_t b0, uint32_t b1) {
    asm volatile(
        "mma.sync.aligned.m16n8k16.row.col.f32.bf16.bf16.f32 "
        "{%0,%1,%2,%3}, {%4,%5,%6,%7}, {%8,%9}, {%0,%1,%2,%3};"
        : "+f"(d[0]), "+f"(d[1]), "+f"(d[2]), "+f"(d[3])
        : "r"(a[0]), "r"(a[1]), "r"(a[2]), "r"(a[3]), "r"(b0), "r"(b1));
}

__device__ __forceinline__ float ex2(float x) {
    float y;
    asm("ex2.approx.ftz.f32 %0, %1;" : "=f"(y) : "f"(x));
    return y;
}

__device__ __forceinline__ void cpasync16(uint32_t saddr, const void* g) {
    asm volatile("cp.async.cg.shared.global [%0], [%1], 16;"
                 :: "r"(saddr), "l"(g));
}
#define CP_COMMIT() asm volatile("cp.async.commit_group;" ::: "memory")
#define CP_WAIT0()  asm volatile("cp.async.wait_group 0;" ::: "memory")
#define CP_WAIT1()  asm volatile("cp.async.wait_group 1;" ::: "memory")

// pack (a -> low, b -> high) as bf16x2, plus residual lo pair
__device__ __forceinline__ void split_pair(float a, float b,
                                           uint32_t& hi, uint32_t& lo) {
    uint32_t h;
    asm("cvt.rn.bf16x2.f32 %0, %1, %2;" : "=r"(h) : "f"(b), "f"(a));
    float ha = __uint_as_float(h << 16);
    float hb = __uint_as_float(h & 0xffff0000u);
    uint32_t l;
    asm("cvt.rn.bf16x2.f32 %0, %1, %2;" : "=r"(l) : "f"(b - hb), "f"(a - ha));
    hi = h;
    lo = l;
}

// ---------------- lengths ----------------------------------------------------
__global__ void len_kernel(const int* __restrict__ mask) {
    int b = blockIdx.x;
    int t = threadIdx.x;
    int s = 0;
    for (int i = t; i < S; i += 256) s += mask[b*S + i];
    __shared__ int sh[256];
    sh[t] = s;
    __syncthreads();
    for (int o = 128; o > 0; o >>= 1) {
        if (t < o) sh[t] += sh[t + o];
        __syncthreads();
    }
    if (t == 0) g_len[b] = sh[0];
}

// ---------------- fp32 -> bf16 hi/lo decomposition ---------------------------
__global__ __launch_bounds__(256)
void decomp_kernel(const float* __restrict__ x, __nv_bfloat16* __restrict__ hi,
                   __nv_bfloat16* __restrict__ lo, int n4) {
    int i = blockIdx.x * 256 + threadIdx.x;
    if (i >= n4) return;
    float4 v = ((const float4*)x)[i];
    float f[4] = {v.x, v.y, v.z, v.w};
    #pragma unroll
    for (int j = 0; j < 4; j++) {
        __nv_bfloat16 h = __float2bfloat16(f[j]);
        hi[4*i + j] = h;
        lo[4*i + j] = __float2bfloat16(f[j] - __bfloat162float(h));
    }
}

// all 4 weight matrices in one launch; Wq (y==0) pre-scaled by CEXP
__global__ __launch_bounds__(256)
void decompw_kernel(const float* __restrict__ w0, const float* __restrict__ w1,
                    const float* __restrict__ w2, const float* __restrict__ w3,
                    __nv_bfloat16* __restrict__ hi, __nv_bfloat16* __restrict__ lo) {
    int m = blockIdx.y;
    const float* src = (m == 0) ? w0 : (m == 1) ? w1 : (m == 2) ? w2 : w3;
    float sc = (m == 0) ? CEXP : 1.0f;
    int i = blockIdx.x * 256 + threadIdx.x;           // over E*E/4
    float4 v = ((const float4*)src)[i];
    float f[4] = {v.x * sc, v.y * sc, v.z * sc, v.w * sc};
    size_t base = (size_t)m * E * E + 4 * (size_t)i;
    #pragma unroll
    for (int j = 0; j < 4; j++) {
        __nv_bfloat16 h = __float2bfloat16(f[j]);
        hi[base + j] = h;
        lo[base + j] = __float2bfloat16(f[j] - __bfloat162float(h));
    }
}

// ---------------- mma.sync bf16x3 GEMM core ----------------------------------
// CTA 128x128, 512 threads, warp tile 32x32, K chunks of 64 double-buffered.
#define GPITCH 144
#define GCHUNKB (128 * GPITCH)
#define GBUFB (4 * GCHUNKB)
#define GEMM_SMEM (2 * GBUFB)                 // 147456

__device__ __forceinline__ void gemm_core(
    const __nv_bfloat16* __restrict__ Ahi, const __nv_bfloat16* __restrict__ Alo,
    const __nv_bfloat16* __restrict__ Bhi, const __nv_bfloat16* __restrict__ Blo,
    float* __restrict__ Yf,
    __nv_bfloat16* __restrict__ Yhi, __nv_bfloat16* __restrict__ Ylo,
    char* smem) {
    const int bm = blockIdx.x * 128;
    const int bn = blockIdx.y * 128;
    const int tid = threadIdx.x;
    const int lane = tid & 31;
    const int wid = tid >> 5;
    const int wm = (wid & 3) * 32;
    const int wn = (wid >> 2) * 32;
    const uint32_t base = smem_u32(smem);

    float acc[2][4][4];
    #pragma unroll
    for (int mi = 0; mi < 2; mi++)
        #pragma unroll
        for (int ni = 0; ni < 4; ni++)
            #pragma unroll
            for (int k = 0; k < 4; k++) acc[mi][ni][k] = 0.f;

    const int a_row = lane & 15;
    const int a_kb  = (lane >> 4) * 16;
    const int pr0 = tid >> 3, pc0 = tid & 7;            // prefetch row/col (i=0)
    const int pr1 = (tid + 512) >> 3, pc1 = (tid + 512) & 7;

    float4 pf[8];
    #define PFLOAD(k0) do { \
        size_t g0 = (size_t)pr0 * E + (k0) + pc0 * 8; \
        size_t g1 = (size_t)pr1 * E + (k0) + pc1 * 8; \
        pf[0] = *(const float4*)(Ahi + (size_t)bm * E + g0); \
        pf[1] = *(const float4*)(Alo + (size_t)bm * E + g0); \
        pf[2] = *(const float4*)(Bhi + (size_t)bn * E + g0); \
        pf[3] = *(const float4*)(Blo + (size_t)bn * E + g0); \
        pf[4] = *(const float4*)(Ahi + (size_t)bm * E + g1); \
        pf[5] = *(const float4*)(Alo + (size_t)bm * E + g1); \
        pf[6] = *(const float4*)(Bhi + (size_t)bn * E + g1); \
        pf[7] = *(const float4*)(Blo + (size_t)bn * E + g1); \
    } while (0)
    #define PFSTORE(buf) do { \
        char* bp = smem + (buf) * GBUFB; \
        int s0 = pr0 * GPITCH + pc0 * 16; \
        int s1 = pr1 * GPITCH + pc1 * 16; \
        *(float4*)(bp + s0)               = pf[0]; \
        *(float4*)(bp + GCHUNKB + s0)     = pf[1]; \
        *(float4*)(bp + 2 * GCHUNKB + s0) = pf[2]; \
        *(float4*)(bp + 3 * GCHUNKB + s0) = pf[3]; \
        *(float4*)(bp + s1)               = pf[4]; \
        *(float4*)(bp + GCHUNKB + s1)     = pf[5]; \
        *(float4*)(bp + 2 * GCHUNKB + s1) = pf[6]; \
        *(float4*)(bp + 3 * GCHUNKB + s1) = pf[7]; \
    } while (0)

    PFLOAD(0);
    PFSTORE(0);
    __syncthreads();

    for (int kc = 0; kc < 4; kc++) {
        if (kc < 3) PFLOAD((kc + 1) * 64);
        const uint32_t uA = base + (kc & 1) * GBUFB;
        const uint32_t uB = uA + 2 * GCHUNKB;

        #pragma unroll
        for (int ks = 0; ks < 4; ks++) {
            const int kb = ks * 32;
            uint32_t ahi[2][4], alo[2][4], bhi[4][2], blo[4][2];
            #pragma unroll
            for (int mi = 0; mi < 2; mi++) {
                uint32_t off = (uint32_t)((wm + mi * 16 + a_row) * GPITCH + kb + a_kb);
                ldsm4(ahi[mi], uA + off);
                ldsm4(alo[mi], uA + GCHUNKB + off);
            }
            #pragma unroll
            for (int np = 0; np < 2; np++) {
                uint32_t off = (uint32_t)((wn + np * 16 + a_row) * GPITCH + kb + a_kb);
                uint32_t th[4], tl[4];
                ldsm4(th, uB + off);
                ldsm4(tl, uB + GCHUNKB + off);
                bhi[np*2][0] = th[0]; bhi[np*2][1] = th[2];
                bhi[np*2+1][0] = th[1]; bhi[np*2+1][1] = th[3];
                blo[np*2][0] = tl[0]; blo[np*2][1] = tl[2];
                blo[np*2+1][0] = tl[1]; blo[np*2+1][1] = tl[3];
            }
            #pragma unroll
            for (int mi = 0; mi < 2; mi++)
                #pragma unroll
                for (int ni = 0; ni < 4; ni++) {
                    mma16816(acc[mi][ni], ahi[mi], bhi[ni][0], bhi[ni][1]);
                    mma16816(acc[mi][ni], ahi[mi], blo[ni][0], blo[ni][1]);
                    mma16816(acc[mi][ni], alo[mi], bhi[ni][0], bhi[ni][1]);
                }
        }
        if (kc < 3) {
            PFSTORE((kc + 1) & 1);
            __syncthreads();
        }
    }

    const int g = lane >> 2;
    const int t2 = (lane & 3) * 2;
    #pragma unroll
    for (int mi = 0; mi < 2; mi++)
        #pragma unroll
        for (int ni = 0; ni < 4; ni++) {
            int row = bm + wm + mi * 16 + g;
            int col = bn + wn + ni * 8 + t2;
            if (Yf) {
                *(float2*)&Yf[(size_t)row * E + col] =
                    make_float2(acc[mi][ni][0], acc[mi][ni][1]);
                *(float2*)&Yf[(size_t)(row + 8) * E + col] =
                    make_float2(acc[mi][ni][2], acc[mi][ni][3]);
            } else {
                uint32_t h0, l0, h1, l1;
                split_pair(acc[mi][ni][0], acc[mi][ni][1], h0, l0);
                split_pair(acc[mi][ni][2], acc[mi][ni][3], h1, l1);
                *(uint32_t*)(Yhi + (size_t)row * E + col) = h0;
                *(uint32_t*)(Ylo + (size_t)row * E + col) = l0;
                *(uint32_t*)(Yhi + (size_t)(row + 8) * E + col) = h1;
                *(uint32_t*)(Ylo + (size_t)(row + 8) * E + col) = l1;
            }
        }
    #undef PFLOAD
    #undef PFSTORE
}

struct QKVOuts {
    __nv_bfloat16 *h0, *l0, *h1, *l1, *h2, *l2;
};

// fused Q/K/V projections: grid.z selects weight + destination
__global__ __launch_bounds__(512, 1)
void gemm_qkv(const __nv_bfloat16* __restrict__ xhi, const __nv_bfloat16* __restrict__ xlo,
              const __nv_bfloat16* __restrict__ whi, const __nv_bfloat16* __restrict__ wlo,
              QKVOuts o) {
    extern __shared__ char smem[];
    const int z = blockIdx.z;
    const __nv_bfloat16* Bh = whi + (size_t)z * E * E;
    const __nv_bfloat16* Bl = wlo + (size_t)z * E * E;
    __nv_bfloat16* Yh = (z == 0) ? o.h0 : (z == 1) ? o.h1 : o.h2;
    __nv_bfloat16* Yl = (z == 0) ? o.l0 : (z == 1) ? o.l1 : o.l2;
    gemm_core(xhi, xlo, Bh, Bl, nullptr, Yh, Yl, smem);
}

__global__ __launch_bounds__(512, 1)
void gemm_out(const __nv_bfloat16* __restrict__ phi, const __nv_bfloat16* __restrict__ plo,
              const __nv_bfloat16* __restrict__ whi, const __nv_bfloat16* __restrict__ wlo,
              float* __restrict__ Yf) {
    extern __shared__ char smem[];
    gemm_core(phi, plo, whi, wlo, Yf, nullptr, nullptr, smem);
}

// ---------------- tensor-core varlen flash attention --------------------------
// CTA: 128 queries of one (b,h); 4 warps x 32 q-rows; key tiles of 64.
// K and V stored row-major (pitch 80); cp.async double-buffered K/V tiles.
// PV uses ldmatrix.trans on row-major V.
#define PQ 80
#define SM_KV (2 * 128 * PQ)                  // Q region: 20480
#define KVBUF (256 * PQ)                      // Khi|Klo|Vhi|Vlo, 64 rows each: 20480
#define ATTN_SMEM (SM_KV + 2 * KVBUF)         // 61440

__global__ __launch_bounds__(128)
void attn_mma() {
    const int b = blockIdx.z;
    const int h = blockIdx.y;
    const int L = g_len[b];
    const int qt = blockIdx.x * 128;
    if (qt >= L) return;

    extern __shared__ char sm[];
    const uint32_t uQh = smem_u32(sm);

    const int tid = threadIdx.x;
    const int lane = tid & 31;
    const int w = tid >> 5;
    const int wq = w * 32;
    const int g = lane >> 2;
    const int t2 = (lane & 3) * 2;

    // cp.async issue geometry: 8 x 16B per thread per tile
    const int pr = tid >> 2;                   // 0..31 (advances by 32 per iter)
    const int pc = tid & 3;                    // 16B column within 64B row

    #define KV_ISSUE(k0, buf) do { \
        uint32_t dbase = uQh + SM_KV + (buf) * KVBUF; \
        _Pragma("unroll") \
        for (int i = 0; i < 8; i++) { \
            int r = pr + i * 32;               /* 0..255 */ \
            int region = r >> 6, rr = r & 63; \
            const __nv_bfloat16* src = \
                (region == 0) ? g_khi : (region == 1) ? g_klo : \
                (region == 2) ? g_vhi : g_vlo; \
            cpasync16(dbase + r * PQ + pc * 16, \
                      src + ((size_t)(b * S + (k0) + rr)) * E + h * D + pc * 8); \
        } \
    } while (0)

    // ---- stage Q tile (128 rows x 32 cols = 64B/row, hi+lo) ----
    {
        int r = tid;
        size_t off = ((size_t)(b * S + qt + r)) * E + h * D;
        const uint4* sh = (const uint4*)(g_qhi + off);
        const uint4* sl = (const uint4*)(g_qlo + off);
        #pragma unroll
        for (int j = 0; j < 4; j++) {
            *(uint4*)(sm + r * PQ + 16 * j)            = sh[j];
            *(uint4*)(sm + 128 * PQ + r * PQ + 16 * j) = sl[j];
        }
    }
    KV_ISSUE(0, 0);
    CP_COMMIT();
    __syncthreads();

    // Q fragments (kept in registers for the whole kernel)
    uint32_t qh[2][2][4], ql[2][2][4];
    #pragma unroll
    for (int mi = 0; mi < 2; mi++)
        #pragma unroll
        for (int s = 0; s < 2; s++) {
            uint32_t ad = uQh + (wq + mi * 16 + (lane & 15)) * PQ
                        + (lane >> 4) * 16 + s * 32;
            ldsm4(qh[mi][s], ad);
            ldsm4(ql[mi][s], ad + 128 * PQ);
        }

    float mx[2][2], lsum[2][2], acc[2][4][4];
    #pragma unroll
    for (int mi = 0; mi < 2; mi++)
        #pragma unroll
        for (int hf = 0; hf < 2; hf++) { mx[mi][hf] = -1e30f; lsum[mi][hf] = 0.f; }
    #pragma unroll
    for (int mi = 0; mi < 2; mi++)
        #pragma unroll
        for (int nd = 0; nd < 4; nd++)
            #pragma unroll
            for (int c = 0; c < 4; c++) acc[mi][nd][c] = 0.f;

    const int ntiles = (L + 63) >> 6;
    for (int t = 0; t < ntiles; t++) {
        const int tn = min(64, L - t * 64);
        if (t + 1 < ntiles) {
            KV_ISSUE((t + 1) * 64, (t + 1) & 1);
            CP_COMMIT();
            CP_WAIT1();
        } else {
            CP_WAIT0();
        }
        __syncthreads();

        const uint32_t uK = uQh + SM_KV + (t & 1) * KVBUF;       // Khi
        const uint32_t uV = uK + 128 * PQ;                        // Vhi

        // ---- scores: S[32q x 64k] per warp, bf16x3 compensated ----
        float sc[2][8][4];
        #pragma unroll
        for (int mi = 0; mi < 2; mi++)
            #pragma unroll
            for (int nj = 0; nj < 8; nj++)
                #pragma unroll
                for (int c = 0; c < 4; c++) sc[mi][nj][c] = 0.f;

        #pragma unroll
        for (int njp = 0; njp < 4; njp++) {
            uint32_t kh[2][4], kl[2][4];
            #pragma unroll
            for (int s = 0; s < 2; s++) {
                uint32_t ad = uK + (njp * 16 + (lane & 15)) * PQ
                            + (lane >> 4) * 16 + s * 32;
                ldsm4(kh[s], ad);
                ldsm4(kl[s], ad + 64 * PQ);
            }
            #pragma unroll
            for (int mi = 0; mi < 2; mi++)
                #pragma unroll
                for (int j2 = 0; j2 < 2; j2++) {
                    float* dst = sc[mi][njp * 2 + j2];
                    #pragma unroll
                    for (int s = 0; s < 2; s++) {
                        mma16816(dst, qh[mi][s], kh[s][j2], kh[s][2 + j2]);
                        mma16816(dst, qh[mi][s], kl[s][j2], kl[s][2 + j2]);
                        mma16816(dst, ql[mi][s], kh[s][j2], kh[s][2 + j2]);
                    }
                }
        }

        // ---- mask tail keys ----
        if (tn < 64) {
            #pragma unroll
            for (int mi = 0; mi < 2; mi++)
                #pragma unroll
                for (int nj = 0; nj < 8; nj++)
                    #pragma unroll
                    for (int c = 0; c < 4; c++) {
                        int kc = nj * 8 + t2 + (c & 1);
                        if (kc >= tn) sc[mi][nj][c] = -1e30f;
                    }
        }

        // ---- online softmax (per row; rows g and g+8 of each m-tile) ----
        #pragma unroll
        for (int mi = 0; mi < 2; mi++)
            #pragma unroll
            for (int hf = 0; hf < 2; hf++) {
                float vmax = -1e30f;
                #pragma unroll
                for (int nj = 0; nj < 8; nj++) {
                    vmax = fmaxf(vmax, sc[mi][nj][hf * 2]);
                    vmax = fmaxf(vmax, sc[mi][nj][hf * 2 + 1]);
                }
                vmax = fmaxf(vmax, __shfl_xor_sync(0xffffffffu, vmax, 1));
                vmax = fmaxf(vmax, __shfl_xor_sync(0xffffffffu, vmax, 2));
                float mold = mx[mi][hf];
                float mnew = fmaxf(mold, vmax);
                mx[mi][hf] = mnew;
                float rs = ex2(mold - mnew);
                lsum[mi][hf] *= rs;
                #pragma unroll
                for (int nd = 0; nd < 4; nd++) {
                    acc[mi][nd][hf * 2] *= rs;
                    acc[mi][nd][hf * 2 + 1] *= rs;
                }
                float rowsum = 0.f;
                #pragma unroll
                for (int nj = 0; nj < 8; nj++) {
                    float p0 = ex2(sc[mi][nj][hf * 2] - mnew);
                    float p1 = ex2(sc[mi][nj][hf * 2 + 1] - mnew);
                    sc[mi][nj][hf * 2] = p0;
                    sc[mi][nj][hf * 2 + 1] = p1;
                    rowsum += p0 + p1;
                }
                rowsum += __shfl_xor_sync(0xffffffffu, rowsum, 1);
                rowsum += __shfl_xor_sync(0xffffffffu, rowsum, 2);
                lsum[mi][hf] += rowsum;
            }

        // ---- PV: O += P * V, bf16x3 compensated; V row-major + ldsm.trans ----
        #pragma unroll
        for (int s = 0; s < 4; s++) {          // k16 steps
            uint32_t ph[2][4], pl[2][4];
            #pragma unroll
            for (int mi = 0; mi < 2; mi++) {
                float* c0 = sc[mi][2 * s];
                float* c1 = sc[mi][2 * s + 1];
                split_pair(c0[0], c0[1], ph[mi][0], pl[mi][0]);
                split_pair(c0[2], c0[3], ph[mi][1], pl[mi][1]);
                split_pair(c1[0], c1[1], ph[mi][2], pl[mi][2]);
                split_pair(c1[2], c1[3], ph[mi][3], pl[mi][3]);
            }
            #pragma unroll
            for (int dp = 0; dp < 2; dp++) {   // d-octet pairs
                // trans ldsm: 4 8x8 blocks (k s*16|s*16+8) x (d dp*16|dp*16+8)
                uint32_t ad = uV + (s * 16 + (lane & 7) + ((lane >> 3) & 1) * 8) * PQ
                            + dp * 32 + (lane >> 4) * 16;
                uint32_t vh[4], vl[4];
                ldsm4t(vh, ad);
                ldsm4t(vl, ad + 64 * PQ);
                #pragma unroll
                for (int mi = 0; mi < 2; mi++) {
                    mma16816(acc[mi][2*dp],   ph[mi], vh[0], vh[1]);
                    mma16816(acc[mi][2*dp],   pl[mi], vh[0], vh[1]);
                    mma16816(acc[mi][2*dp],   ph[mi], vl[0], vl[1]);
                    mma16816(acc[mi][2*dp+1], ph[mi], vh[2], vh[3]);
                    mma16816(acc[mi][2*dp+1], pl[mi], vh[2], vh[3]);
                    mma16816(acc[mi][2*dp+1], ph[mi], vl[2], vl[3]);
                }
            }
        }
        __syncthreads();                       // buffer reuse safety
    }

    // ---- epilogue: O/l, hi/lo split, scrambled-layout write ----
    #pragma unroll
    for (int mi = 0; mi < 2; mi++)
        #pragma unroll
        for (int hf = 0; hf < 2; hf++) {
            int q = qt + wq + mi * 16 + g + hf * 8;
            if (q < L) {
                float inv = 1.f / lsum[mi][hf];
                #pragma unroll
                for (int nd = 0; nd < 4; nd++) {
                    float o0 = acc[mi][nd][hf * 2] * inv;
                    float o1 = acc[mi][nd][hf * 2 + 1] * inv;
                    uint32_t hh, ll;
                    split_pair(o0, o1, hh, ll);
                    size_t off = (size_t)b * S * E + ((size_t)h * L + q) * D
                               + nd * 8 + t2;
                    *(uint32_t*)(g_phi + off) = hh;
                    *(uint32_t*)(g_plo + off) = ll;
                }
            }
        }
    #undef KV_ISSUE
}

// ---------------- launch ------------------------------------------------------
extern "C" void kernel_launch(void* const* d_in, const int* in_sizes, int n_in,
                              void* d_out, int out_size) {
    const float* x    = (const float*)d_in[0];
    const int*   mask = (const int*)  d_in[1];
    const float* Wq   = (const float*)d_in[2];
    const float* Wk   = (const float*)d_in[3];
    const float* Wv   = (const float*)d_in[4];
    const float* Wo   = (const float*)d_in[5];
    float* out = (float*)d_out;

    __nv_bfloat16 *xhi, *xlo, *qhi, *qlo, *khi, *klo, *vhi, *vlo, *phi, *plo, *whi, *wlo;
    cudaGetSymbolAddress((void**)&xhi, g_xhi);
    cudaGetSymbolAddress((void**)&xlo, g_xlo);
    cudaGetSymbolAddress((void**)&qhi, g_qhi);
    cudaGetSymbolAddress((void**)&qlo, g_qlo);
    cudaGetSymbolAddress((void**)&khi, g_khi);
    cudaGetSymbolAddress((void**)&klo, g_klo);
    cudaGetSymbolAddress((void**)&vhi, g_vhi);
    cudaGetSymbolAddress((void**)&vlo, g_vlo);
    cudaGetSymbolAddress((void**)&phi, g_phi);
    cudaGetSymbolAddress((void**)&plo, g_plo);
    cudaGetSymbolAddress((void**)&whi, g_whi);
    cudaGetSymbolAddress((void**)&wlo, g_wlo);

    cudaFuncSetAttribute(gemm_qkv, cudaFuncAttributeMaxDynamicSharedMemorySize,
                         GEMM_SMEM);
    cudaFuncSetAttribute(gemm_out, cudaFuncAttributeMaxDynamicSharedMemorySize,
                         GEMM_SMEM);
    cudaFuncSetAttribute(attn_mma, cudaFuncAttributeMaxDynamicSharedMemorySize,
                         ATTN_SMEM);

    len_kernel<<<B, 256>>>(mask);
    cudaMemsetAsync(phi, 0, (size_t)M * E * sizeof(__nv_bfloat16), 0);
    cudaMemsetAsync(plo, 0, (size_t)M * E * sizeof(__nv_bfloat16), 0);

    decomp_kernel<<<(M*E/4 + 255)/256, 256>>>(x, xhi, xlo, M*E/4);
    decompw_kernel<<<dim3(E*E/4/256, 4), 256>>>(Wq, Wk, Wv, Wo, whi, wlo);

    QKVOuts o = { qhi, qlo, khi, klo, vhi, vlo };
    dim3 gq(M / 128, E / 128, 3);
    gemm_qkv<<<gq, 512, GEMM_SMEM>>>(xhi, xlo, whi, wlo, o);

    dim3 ga(S / 128, H, B);
    attn_mma<<<ga, 128, ATTN_SMEM>>>();

    dim3 gg(M / 128, E / 128);
    gemm_out<<<gg, 512, GEMM_SMEM>>>(phi, plo, whi + 3*E*E, wlo + 3*E*E, out);
}

// round 8
// speedup vs baseline: 4.3839x; 1.0540x over previous
#include <cuda_runtime.h>
#include <cuda_bf16.h>
#include <stdint.h>

#define B 4
#define S 2048
#define E 256
#define H 8
#define D 32
#define M (B*S)
// SCALE * log2(e), folded into Wq at decomposition time
#define CEXP (0.17677669529663687f * 1.44269504088896341f)

// ---------------- scratch (device globals; no allocation allowed) ----------
static __device__ __align__(16) __nv_bfloat16 g_xhi[M*E];
static __device__ __align__(16) __nv_bfloat16 g_xlo[M*E];
static __device__ __align__(16) __nv_bfloat16 g_qhi[M*E];
static __device__ __align__(16) __nv_bfloat16 g_qlo[M*E];
static __device__ __align__(16) __nv_bfloat16 g_khi[M*E];
static __device__ __align__(16) __nv_bfloat16 g_klo[M*E];
static __device__ __align__(16) __nv_bfloat16 g_vhi[M*E];
static __device__ __align__(16) __nv_bfloat16 g_vlo[M*E];
static __device__ __align__(16) __nv_bfloat16 g_phi[M*E];
static __device__ __align__(16) __nv_bfloat16 g_plo[M*E];
static __device__ __align__(16) __nv_bfloat16 g_whi[4*E*E];
static __device__ __align__(16) __nv_bfloat16 g_wlo[4*E*E];
static __device__ int g_len[B];

// ---------------- helpers ----------------------------------------------------
__device__ __forceinline__ uint32_t smem_u32(const void* p) {
    uint32_t a;
    asm("{ .reg .u64 t; cvta.to.shared.u64 t, %1; cvt.u32.u64 %0, t; }"
        : "=r"(a) : "l"(p));
    return a;
}

__device__ __forceinline__ void ldsm4(uint32_t* r, uint32_t addr) {
    asm volatile("ldmatrix.sync.aligned.m8n8.x4.shared.b16 {%0,%1,%2,%3}, [%4];"
                 : "=r"(r[0]), "=r"(r[1]), "=r"(r[2]), "=r"(r[3]) : "r"(addr));
}

__device__ __forceinline__ void ldsm4t(uint32_t* r, uint32_t addr) {
    asm volatile("ldmatrix.sync.aligned.m8n8.x4.trans.shared.b16 {%0,%1,%2,%3}, [%4];"
                 : "=r"(r[0]), "=r"(r[1]), "=r"(r[2]), "=r"(r[3]) : "r"(addr));
}

__device__ __forceinline__ void mma16816(float* d, const uint32_t* a,
                                         uint32_t b0, uint32_t b1) {
    asm volatile(
        "mma.sync.aligned.m16n8k16.row.col.f32.bf16.bf16.f32 "
        "{%0,%1,%2,%3}, {%4,%5,%6,%7}, {%8,%9}, {%0,%1,%2,%3};"
        : "+f"(d[0]), "+f"(d[1]), "+f"(d[2]), "+f"(d[3])
        : "r"(a[0]), "r"(a[1]), "r"(a[2]), "r"(a[3]), "r"(b0), "r"(b1));
}

__device__ __forceinline__ float ex2(float x) {
    float y;
    asm("ex2.approx.ftz.f32 %0, %1;" : "=f"(y) : "f"(x));
    return y;
}

__device__ __forceinline__ void cpasync16(uint32_t saddr, const void* g) {
    asm volatile("cp.async.cg.shared.global [%0], [%1], 16;"
                 :: "r"(saddr), "l"(g));
}
#define CP_COMMIT() asm volatile("cp.async.commit_group;" ::: "memory")
#define CP_WAIT0()  asm volatile("cp.async.wait_group 0;" ::: "memory")
#define CP_WAIT1()  asm volatile("cp.async.wait_group 1;" ::: "memory")

// pack (a -> low, b -> high) as bf16x2, plus residual lo pair
__device__ __forceinline__ void split_pair(float a, float b,
                                           uint32_t& hi, uint32_t& lo) {
    uint32_t h;
    asm("cvt.rn.bf16x2.f32 %0, %1, %2;" : "=r"(h) : "f"(b), "f"(a));
    float ha = __uint_as_float(h << 16);
    float hb = __uint_as_float(h & 0xffff0000u);
    uint32_t l;
    asm("cvt.rn.bf16x2.f32 %0, %1, %2;" : "=r"(l) : "f"(b - hb), "f"(a - ha));
    hi = h;
    lo = l;
}

// ---------------- lengths ----------------------------------------------------
__global__ void len_kernel(const int* __restrict__ mask) {
    int b = blockIdx.x;
    int t = threadIdx.x;
    int s = 0;
    for (int i = t; i < S; i += 256) s += mask[b*S + i];
    __shared__ int sh[256];
    sh[t] = s;
    __syncthreads();
    for (int o = 128; o > 0; o >>= 1) {
        if (t < o) sh[t] += sh[t + o];
        __syncthreads();
    }
    if (t == 0) g_len[b] = sh[0];
}

// ---------------- fp32 -> bf16 hi/lo decomposition ---------------------------
__global__ __launch_bounds__(256)
void decomp_kernel(const float* __restrict__ x, __nv_bfloat16* __restrict__ hi,
                   __nv_bfloat16* __restrict__ lo, int n4) {
    int i = blockIdx.x * 256 + threadIdx.x;
    if (i >= n4) return;
    float4 v = ((const float4*)x)[i];
    float f[4] = {v.x, v.y, v.z, v.w};
    #pragma unroll
    for (int j = 0; j < 4; j++) {
        __nv_bfloat16 h = __float2bfloat16(f[j]);
        hi[4*i + j] = h;
        lo[4*i + j] = __float2bfloat16(f[j] - __bfloat162float(h));
    }
}

// all 4 weight matrices in one launch; Wq (y==0) pre-scaled by CEXP
__global__ __launch_bounds__(256)
void decompw_kernel(const float* __restrict__ w0, const float* __restrict__ w1,
                    const float* __restrict__ w2, const float* __restrict__ w3,
                    __nv_bfloat16* __restrict__ hi, __nv_bfloat16* __restrict__ lo) {
    int m = blockIdx.y;
    const float* src = (m == 0) ? w0 : (m == 1) ? w1 : (m == 2) ? w2 : w3;
    float sc = (m == 0) ? CEXP : 1.0f;
    int i = blockIdx.x * 256 + threadIdx.x;           // over E*E/4
    float4 v = ((const float4*)src)[i];
    float f[4] = {v.x * sc, v.y * sc, v.z * sc, v.w * sc};
    size_t base = (size_t)m * E * E + 4 * (size_t)i;
    #pragma unroll
    for (int j = 0; j < 4; j++) {
        __nv_bfloat16 h = __float2bfloat16(f[j]);
        hi[base + j] = h;
        lo[base + j] = __float2bfloat16(f[j] - __bfloat162float(h));
    }
}

// ---------------- mma.sync bf16x3 GEMM core ----------------------------------
// CTA 128x128, 512 threads, warp tile 32x32, K chunks of 64 double-buffered.
#define GPITCH 144
#define GCHUNKB (128 * GPITCH)
#define GBUFB (4 * GCHUNKB)
#define GEMM_SMEM (2 * GBUFB)                 // 147456

__device__ __forceinline__ void gemm_core(
    const __nv_bfloat16* __restrict__ Ahi, const __nv_bfloat16* __restrict__ Alo,
    const __nv_bfloat16* __restrict__ Bhi, const __nv_bfloat16* __restrict__ Blo,
    float* __restrict__ Yf,
    __nv_bfloat16* __restrict__ Yhi, __nv_bfloat16* __restrict__ Ylo,
    char* smem) {
    const int bm = blockIdx.x * 128;
    const int bn = blockIdx.y * 128;
    const int tid = threadIdx.x;
    const int lane = tid & 31;
    const int wid = tid >> 5;
    const int wm = (wid & 3) * 32;
    const int wn = (wid >> 2) * 32;
    const uint32_t base = smem_u32(smem);

    float acc[2][4][4];
    #pragma unroll
    for (int mi = 0; mi < 2; mi++)
        #pragma unroll
        for (int ni = 0; ni < 4; ni++)
            #pragma unroll
            for (int k = 0; k < 4; k++) acc[mi][ni][k] = 0.f;

    const int a_row = lane & 15;
    const int a_kb  = (lane >> 4) * 16;
    const int pr0 = tid >> 3, pc0 = tid & 7;            // prefetch row/col (i=0)
    const int pr1 = (tid + 512) >> 3, pc1 = (tid + 512) & 7;

    float4 pf[8];
    #define PFLOAD(k0) do { \
        size_t g0 = (size_t)pr0 * E + (k0) + pc0 * 8; \
        size_t g1 = (size_t)pr1 * E + (k0) + pc1 * 8; \
        pf[0] = *(const float4*)(Ahi + (size_t)bm * E + g0); \
        pf[1] = *(const float4*)(Alo + (size_t)bm * E + g0); \
        pf[2] = *(const float4*)(Bhi + (size_t)bn * E + g0); \
        pf[3] = *(const float4*)(Blo + (size_t)bn * E + g0); \
        pf[4] = *(const float4*)(Ahi + (size_t)bm * E + g1); \
        pf[5] = *(const float4*)(Alo + (size_t)bm * E + g1); \
        pf[6] = *(const float4*)(Bhi + (size_t)bn * E + g1); \
        pf[7] = *(const float4*)(Blo + (size_t)bn * E + g1); \
    } while (0)
    #define PFSTORE(buf) do { \
        char* bp = smem + (buf) * GBUFB; \
        int s0 = pr0 * GPITCH + pc0 * 16; \
        int s1 = pr1 * GPITCH + pc1 * 16; \
        *(float4*)(bp + s0)               = pf[0]; \
        *(float4*)(bp + GCHUNKB + s0)     = pf[1]; \
        *(float4*)(bp + 2 * GCHUNKB + s0) = pf[2]; \
        *(float4*)(bp + 3 * GCHUNKB + s0) = pf[3]; \
        *(float4*)(bp + s1)               = pf[4]; \
        *(float4*)(bp + GCHUNKB + s1)     = pf[5]; \
        *(float4*)(bp + 2 * GCHUNKB + s1) = pf[6]; \
        *(float4*)(bp + 3 * GCHUNKB + s1) = pf[7]; \
    } while (0)

    PFLOAD(0);
    PFSTORE(0);
    __syncthreads();

    for (int kc = 0; kc < 4; kc++) {
        if (kc < 3) PFLOAD((kc + 1) * 64);
        const uint32_t uA = base + (kc & 1) * GBUFB;
        const uint32_t uB = uA + 2 * GCHUNKB;

        #pragma unroll
        for (int ks = 0; ks < 4; ks++) {
            const int kb = ks * 32;
            uint32_t ahi[2][4], alo[2][4], bhi[4][2], blo[4][2];
            #pragma unroll
            for (int mi = 0; mi < 2; mi++) {
                uint32_t off = (uint32_t)((wm + mi * 16 + a_row) * GPITCH + kb + a_kb);
                ldsm4(ahi[mi], uA + off);
                ldsm4(alo[mi], uA + GCHUNKB + off);
            }
            #pragma unroll
            for (int np = 0; np < 2; np++) {
                uint32_t off = (uint32_t)((wn + np * 16 + a_row) * GPITCH + kb + a_kb);
                uint32_t th[4], tl[4];
                ldsm4(th, uB + off);
                ldsm4(tl, uB + GCHUNKB + off);
                bhi[np*2][0] = th[0]; bhi[np*2][1] = th[2];
                bhi[np*2+1][0] = th[1]; bhi[np*2+1][1] = th[3];
                blo[np*2][0] = tl[0]; blo[np*2][1] = tl[2];
                blo[np*2+1][0] = tl[1]; blo[np*2+1][1] = tl[3];
            }
            #pragma unroll
            for (int mi = 0; mi < 2; mi++)
                #pragma unroll
                for (int ni = 0; ni < 4; ni++) {
                    mma16816(acc[mi][ni], ahi[mi], bhi[ni][0], bhi[ni][1]);
                    mma16816(acc[mi][ni], ahi[mi], blo[ni][0], blo[ni][1]);
                    mma16816(acc[mi][ni], alo[mi], bhi[ni][0], bhi[ni][1]);
                }
        }
        if (kc < 3) {
            PFSTORE((kc + 1) & 1);
            __syncthreads();
        }
    }

    const int g = lane >> 2;
    const int t2 = (lane & 3) * 2;
    #pragma unroll
    for (int mi = 0; mi < 2; mi++)
        #pragma unroll
        for (int ni = 0; ni < 4; ni++) {
            int row = bm + wm + mi * 16 + g;
            int col = bn + wn + ni * 8 + t2;
            if (Yf) {
                *(float2*)&Yf[(size_t)row * E + col] =
                    make_float2(acc[mi][ni][0], acc[mi][ni][1]);
                *(float2*)&Yf[(size_t)(row + 8) * E + col] =
                    make_float2(acc[mi][ni][2], acc[mi][ni][3]);
            } else {
                uint32_t h0, l0, h1, l1;
                split_pair(acc[mi][ni][0], acc[mi][ni][1], h0, l0);
                split_pair(acc[mi][ni][2], acc[mi][ni][3], h1, l1);
                *(uint32_t*)(Yhi + (size_t)row * E + col) = h0;
                *(uint32_t*)(Ylo + (size_t)row * E + col) = l0;
                *(uint32_t*)(Yhi + (size_t)(row + 8) * E + col) = h1;
                *(uint32_t*)(Ylo + (size_t)(row + 8) * E + col) = l1;
            }
        }
    #undef PFLOAD
    #undef PFSTORE
}

struct QKVOuts {
    __nv_bfloat16 *h0, *l0, *h1, *l1, *h2, *l2;
};

// fused Q/K/V projections: grid.z selects weight + destination
__global__ __launch_bounds__(512, 1)
void gemm_qkv(const __nv_bfloat16* __restrict__ xhi, const __nv_bfloat16* __restrict__ xlo,
              const __nv_bfloat16* __restrict__ whi, const __nv_bfloat16* __restrict__ wlo,
              QKVOuts o) {
    extern __shared__ char smem[];
    const int z = blockIdx.z;
    const __nv_bfloat16* Bh = whi + (size_t)z * E * E;
    const __nv_bfloat16* Bl = wlo + (size_t)z * E * E;
    __nv_bfloat16* Yh = (z == 0) ? o.h0 : (z == 1) ? o.h1 : o.h2;
    __nv_bfloat16* Yl = (z == 0) ? o.l0 : (z == 1) ? o.l1 : o.l2;
    gemm_core(xhi, xlo, Bh, Bl, nullptr, Yh, Yl, smem);
}

__global__ __launch_bounds__(512, 1)
void gemm_out(const __nv_bfloat16* __restrict__ phi, const __nv_bfloat16* __restrict__ plo,
              const __nv_bfloat16* __restrict__ whi, const __nv_bfloat16* __restrict__ wlo,
              float* __restrict__ Yf) {
    extern __shared__ char smem[];
    gemm_core(phi, plo, whi, wlo, Yf, nullptr, nullptr, smem);
}

// ---------------- tensor-core varlen flash attention --------------------------
// CTA: 128 queries of one (b,h); 4 warps x 32 q-rows; key tiles of 64.
// K and V stored row-major (pitch 80); cp.async double-buffered K/V tiles.
// Fixed-base softmax (no online max): p = 2^s, safe since |s|_log2 < ~16.
#define PQ 80
#define SM_KV (2 * 128 * PQ)                  // Q region: 20480
#define KVBUF (256 * PQ)                      // Khi|Klo|Vhi|Vlo, 64 rows each: 20480
#define ATTN_SMEM (SM_KV + 2 * KVBUF)         // 61440

__global__ __launch_bounds__(128, 2)
void attn_mma() {
    const int b = blockIdx.z;
    const int h = blockIdx.y;
    const int L = g_len[b];
    const int qt = blockIdx.x * 128;
    if (qt >= L) return;

    extern __shared__ char sm[];
    const uint32_t uQh = smem_u32(sm);

    const int tid = threadIdx.x;
    const int lane = tid & 31;
    const int w = tid >> 5;
    const int wq = w * 32;
    const int g = lane >> 2;
    const int t2 = (lane & 3) * 2;

    // cp.async issue geometry: 8 x 16B per thread per tile
    const int pr = tid >> 2;                   // 0..31 (advances by 32 per iter)
    const int pc = tid & 3;                    // 16B column within 64B row

    #define KV_ISSUE(k0, buf) do { \
        uint32_t dbase = uQh + SM_KV + (buf) * KVBUF; \
        _Pragma("unroll") \
        for (int i = 0; i < 8; i++) { \
            int r = pr + i * 32;               /* 0..255 */ \
            int region = r >> 6, rr = r & 63; \
            const __nv_bfloat16* src = \
                (region == 0) ? g_khi : (region == 1) ? g_klo : \
                (region == 2) ? g_vhi : g_vlo; \
            cpasync16(dbase + r * PQ + pc * 16, \
                      src + ((size_t)(b * S + (k0) + rr)) * E + h * D + pc * 8); \
        } \
    } while (0)

    // ---- stage Q tile (128 rows x 32 cols = 64B/row, hi+lo) ----
    {
        int r = tid;
        size_t off = ((size_t)(b * S + qt + r)) * E + h * D;
        const uint4* sh = (const uint4*)(g_qhi + off);
        const uint4* sl = (const uint4*)(g_qlo + off);
        #pragma unroll
        for (int j = 0; j < 4; j++) {
            *(uint4*)(sm + r * PQ + 16 * j)            = sh[j];
            *(uint4*)(sm + 128 * PQ + r * PQ + 16 * j) = sl[j];
        }
    }
    KV_ISSUE(0, 0);
    CP_COMMIT();
    __syncthreads();

    // Q fragments (kept in registers for the whole kernel)
    uint32_t qh[2][2][4], ql[2][2][4];
    #pragma unroll
    for (int mi = 0; mi < 2; mi++)
        #pragma unroll
        for (int s = 0; s < 2; s++) {
            uint32_t ad = uQh + (wq + mi * 16 + (lane & 15)) * PQ
                        + (lane >> 4) * 16 + s * 32;
            ldsm4(qh[mi][s], ad);
            ldsm4(ql[mi][s], ad + 128 * PQ);
        }

    float lsum[2][2], acc[2][4][4];
    #pragma unroll
    for (int mi = 0; mi < 2; mi++)
        #pragma unroll
        for (int hf = 0; hf < 2; hf++) lsum[mi][hf] = 0.f;
    #pragma unroll
    for (int mi = 0; mi < 2; mi++)
        #pragma unroll
        for (int nd = 0; nd < 4; nd++)
            #pragma unroll
            for (int c = 0; c < 4; c++) acc[mi][nd][c] = 0.f;

    const int ntiles = (L + 63) >> 6;
    for (int t = 0; t < ntiles; t++) {
        const int tn = min(64, L - t * 64);
        if (t + 1 < ntiles) {
            KV_ISSUE((t + 1) * 64, (t + 1) & 1);
            CP_COMMIT();
            CP_WAIT1();
        } else {
            CP_WAIT0();
        }
        __syncthreads();

        const uint32_t uK = uQh + SM_KV + (t & 1) * KVBUF;       // Khi
        const uint32_t uV = uK + 128 * PQ;                        // Vhi

        // ---- scores: S[32q x 64k] per warp, bf16x3 compensated ----
        float sc[2][8][4];
        #pragma unroll
        for (int mi = 0; mi < 2; mi++)
            #pragma unroll
            for (int nj = 0; nj < 8; nj++)
                #pragma unroll
                for (int c = 0; c < 4; c++) sc[mi][nj][c] = 0.f;

        #pragma unroll
        for (int njp = 0; njp < 4; njp++) {
            uint32_t kh[2][4], kl[2][4];
            #pragma unroll
            for (int s = 0; s < 2; s++) {
                uint32_t ad = uK + (njp * 16 + (lane & 15)) * PQ
                            + (lane >> 4) * 16 + s * 32;
                ldsm4(kh[s], ad);
                ldsm4(kl[s], ad + 64 * PQ);
            }
            #pragma unroll
            for (int mi = 0; mi < 2; mi++)
                #pragma unroll
                for (int j2 = 0; j2 < 2; j2++) {
                    float* dst = sc[mi][njp * 2 + j2];
                    #pragma unroll
                    for (int s = 0; s < 2; s++) {
                        mma16816(dst, qh[mi][s], kh[s][j2], kh[s][2 + j2]);
                        mma16816(dst, qh[mi][s], kl[s][j2], kl[s][2 + j2]);
                        mma16816(dst, ql[mi][s], kh[s][j2], kh[s][2 + j2]);
                    }
                }
        }

        // ---- mask tail keys ----
        if (tn < 64) {
            #pragma unroll
            for (int mi = 0; mi < 2; mi++)
                #pragma unroll
                for (int nj = 0; nj < 8; nj++)
                    #pragma unroll
                    for (int c = 0; c < 4; c++) {
                        int kc = nj * 8 + t2 + (c & 1);
                        if (kc >= tn) sc[mi][nj][c] = -1e30f;
                    }
        }

        // ---- fixed-base softmax: p = 2^s (no max subtraction) ----
        #pragma unroll
        for (int mi = 0; mi < 2; mi++)
            #pragma unroll
            for (int hf = 0; hf < 2; hf++) {
                float rowsum = 0.f;
                #pragma unroll
                for (int nj = 0; nj < 8; nj++) {
                    float p0 = ex2(sc[mi][nj][hf * 2]);
                    float p1 = ex2(sc[mi][nj][hf * 2 + 1]);
                    sc[mi][nj][hf * 2] = p0;
                    sc[mi][nj][hf * 2 + 1] = p1;
                    rowsum += p0 + p1;
                }
                rowsum += __shfl_xor_sync(0xffffffffu, rowsum, 1);
                rowsum += __shfl_xor_sync(0xffffffffu, rowsum, 2);
                lsum[mi][hf] += rowsum;
            }

        // ---- PV: O += P * V, bf16x3 compensated; V row-major + ldsm.trans ----
        #pragma unroll
        for (int s = 0; s < 4; s++) {          // k16 steps
            uint32_t ph[2][4], pl[2][4];
            #pragma unroll
            for (int mi = 0; mi < 2; mi++) {
                float* c0 = sc[mi][2 * s];
                float* c1 = sc[mi][2 * s + 1];
                split_pair(c0[0], c0[1], ph[mi][0], pl[mi][0]);
                split_pair(c0[2], c0[3], ph[mi][1], pl[mi][1]);
                split_pair(c1[0], c1[1], ph[mi][2], pl[mi][2]);
                split_pair(c1[2], c1[3], ph[mi][3], pl[mi][3]);
            }
            #pragma unroll
            for (int dp = 0; dp < 2; dp++) {   // d-octet pairs
                uint32_t ad = uV + (s * 16 + (lane & 7) + ((lane >> 3) & 1) * 8) * PQ
                            + dp * 32 + (lane >> 4) * 16;
                uint32_t vh[4], vl[4];
                ldsm4t(vh, ad);
                ldsm4t(vl, ad + 64 * PQ);
                #pragma unroll
                for (int mi = 0; mi < 2; mi++) {
                    mma16816(acc[mi][2*dp],   ph[mi], vh[0], vh[1]);
                    mma16816(acc[mi][2*dp],   pl[mi], vh[0], vh[1]);
                    mma16816(acc[mi][2*dp],   ph[mi], vl[0], vl[1]);
                    mma16816(acc[mi][2*dp+1], ph[mi], vh[2], vh[3]);
                    mma16816(acc[mi][2*dp+1], pl[mi], vh[2], vh[3]);
                    mma16816(acc[mi][2*dp+1], ph[mi], vl[2], vl[3]);
                }
            }
        }
        __syncthreads();                       // buffer reuse safety
    }

    // ---- epilogue: O/l, hi/lo split, scrambled-layout write ----
    #pragma unroll
    for (int mi = 0; mi < 2; mi++)
        #pragma unroll
        for (int hf = 0; hf < 2; hf++) {
            int q = qt + wq + mi * 16 + g + hf * 8;
            if (q < L) {
                float inv = 1.f / lsum[mi][hf];
                #pragma unroll
                for (int nd = 0; nd < 4; nd++) {
                    float o0 = acc[mi][nd][hf * 2] * inv;
                    float o1 = acc[mi][nd][hf * 2 + 1] * inv;
                    uint32_t hh, ll;
                    split_pair(o0, o1, hh, ll);
                    size_t off = (size_t)b * S * E + ((size_t)h * L + q) * D
                               + nd * 8 + t2;
                    *(uint32_t*)(g_phi + off) = hh;
                    *(uint32_t*)(g_plo + off) = ll;
                }
            }
        }
    #undef KV_ISSUE
}

// ---------------- launch ------------------------------------------------------
extern "C" void kernel_launch(void* const* d_in, const int* in_sizes, int n_in,
                              void* d_out, int out_size) {
    const float* x    = (const float*)d_in[0];
    const int*   mask = (const int*)  d_in[1];
    const float* Wq   = (const float*)d_in[2];
    const float* Wk   = (const float*)d_in[3];
    const float* Wv   = (const float*)d_in[4];
    const float* Wo   = (const float*)d_in[5];
    float* out = (float*)d_out;

    __nv_bfloat16 *xhi, *xlo, *qhi, *qlo, *khi, *klo, *vhi, *vlo, *phi, *plo, *whi, *wlo;
    cudaGetSymbolAddress((void**)&xhi, g_xhi);
    cudaGetSymbolAddress((void**)&xlo, g_xlo);
    cudaGetSymbolAddress((void**)&qhi, g_qhi);
    cudaGetSymbolAddress((void**)&qlo, g_qlo);
    cudaGetSymbolAddress((void**)&khi, g_khi);
    cudaGetSymbolAddress((void**)&klo, g_klo);
    cudaGetSymbolAddress((void**)&vhi, g_vhi);
    cudaGetSymbolAddress((void**)&vlo, g_vlo);
    cudaGetSymbolAddress((void**)&phi, g_phi);
    cudaGetSymbolAddress((void**)&plo, g_plo);
    cudaGetSymbolAddress((void**)&whi, g_whi);
    cudaGetSymbolAddress((void**)&wlo, g_wlo);

    cudaFuncSetAttribute(gemm_qkv, cudaFuncAttributeMaxDynamicSharedMemorySize,
                         GEMM_SMEM);
    cudaFuncSetAttribute(gemm_out, cudaFuncAttributeMaxDynamicSharedMemorySize,
                         GEMM_SMEM);
    cudaFuncSetAttribute(attn_mma, cudaFuncAttributeMaxDynamicSharedMemorySize,
                         ATTN_SMEM);

    len_kernel<<<B, 256>>>(mask);
    cudaMemsetAsync(phi, 0, (size_t)M * E * sizeof(__nv_bfloat16), 0);
    cudaMemsetAsync(plo, 0, (size_t)M * E * sizeof(__nv_bfloat16), 0);

    decomp_kernel<<<(M*E/4 + 255)/256, 256>>>(x, xhi, xlo, M*E/4);
    decompw_kernel<<<dim3(E*E/4/256, 4), 256>>>(Wq, Wk, Wv, Wo, whi, wlo);

    QKVOuts o = { qhi, qlo, khi, klo, vhi, vlo };
    dim3 gq(M / 128, E / 128, 3);
    gemm_qkv<<<gq, 512, GEMM_SMEM>>>(xhi, xlo, whi, wlo, o);

    dim3 ga(S / 128, H, B);
    attn_mma<<<ga, 128, ATTN_SMEM>>>();

    dim3 gg(M / 128, E / 128);
    gemm_out<<<gg, 512, GEMM_SMEM>>>(phi, plo, whi + 3*E*E, wlo + 3*E*E, out);
}

// round 9
// speedup vs baseline: 4.5893x; 1.0468x over previous
#include <cuda_runtime.h>
#include <cuda_bf16.h>
#include <stdint.h>

#define B 4
#define S 2048
#define E 256
#define H 8
#define D 32
#define M (B*S)
// SCALE * log2(e), folded into Wq at decomposition time
#define CEXP (0.17677669529663687f * 1.44269504088896341f)

// ---------------- scratch (device globals; no allocation allowed) ----------
static __device__ __align__(16) __nv_bfloat16 g_xhi[M*E];
static __device__ __align__(16) __nv_bfloat16 g_xlo[M*E];
static __device__ __align__(16) __nv_bfloat16 g_qhi[M*E];
static __device__ __align__(16) __nv_bfloat16 g_qlo[M*E];
static __device__ __align__(16) __nv_bfloat16 g_khi[M*E];
static __device__ __align__(16) __nv_bfloat16 g_klo[M*E];
static __device__ __align__(16) __nv_bfloat16 g_vhi[M*E];   // holds fp16 bits
static __device__ __align__(16) __nv_bfloat16 g_vlo[M*E];   // holds fp16 bits
static __device__ __align__(16) __nv_bfloat16 g_phi[M*E];
static __device__ __align__(16) __nv_bfloat16 g_plo[M*E];
static __device__ __align__(16) __nv_bfloat16 g_whi[4*E*E];
static __device__ __align__(16) __nv_bfloat16 g_wlo[4*E*E];
static __device__ int g_len[B];

// ---------------- helpers ----------------------------------------------------
__device__ __forceinline__ uint32_t smem_u32(const void* p) {
    uint32_t a;
    asm("{ .reg .u64 t; cvta.to.shared.u64 t, %1; cvt.u32.u64 %0, t; }"
        : "=r"(a) : "l"(p));
    return a;
}

__device__ __forceinline__ void ldsm4(uint32_t* r, uint32_t addr) {
    asm volatile("ldmatrix.sync.aligned.m8n8.x4.shared.b16 {%0,%1,%2,%3}, [%4];"
                 : "=r"(r[0]), "=r"(r[1]), "=r"(r[2]), "=r"(r[3]) : "r"(addr));
}

__device__ __forceinline__ void ldsm4t(uint32_t* r, uint32_t addr) {
    asm volatile("ldmatrix.sync.aligned.m8n8.x4.trans.shared.b16 {%0,%1,%2,%3}, [%4];"
                 : "=r"(r[0]), "=r"(r[1]), "=r"(r[2]), "=r"(r[3]) : "r"(addr));
}

// bf16 MMA
__device__ __forceinline__ void mma16816(float* d, const uint32_t* a,
                                         uint32_t b0, uint32_t b1) {
    asm volatile(
        "mma.sync.aligned.m16n8k16.row.col.f32.bf16.bf16.f32 "
        "{%0,%1,%2,%3}, {%4,%5,%6,%7}, {%8,%9}, {%0,%1,%2,%3};"
        : "+f"(d[0]), "+f"(d[1]), "+f"(d[2]), "+f"(d[3])
        : "r"(a[0]), "r"(a[1]), "r"(a[2]), "r"(a[3]), "r"(b0), "r"(b1));
}

// fp16 MMA
__device__ __forceinline__ void mma16816h(float* d, const uint32_t* a,
                                          uint32_t b0, uint32_t b1) {
    asm volatile(
        "mma.sync.aligned.m16n8k16.row.col.f32.f16.f16.f32 "
        "{%0,%1,%2,%3}, {%4,%5,%6,%7}, {%8,%9}, {%0,%1,%2,%3};"
        : "+f"(d[0]), "+f"(d[1]), "+f"(d[2]), "+f"(d[3])
        : "r"(a[0]), "r"(a[1]), "r"(a[2]), "r"(a[3]), "r"(b0), "r"(b1));
}

__device__ __forceinline__ float ex2(float x) {
    float y;
    asm("ex2.approx.ftz.f32 %0, %1;" : "=f"(y) : "f"(x));
    return y;
}

__device__ __forceinline__ void cpasync16(uint32_t saddr, const void* g) {
    asm volatile("cp.async.cg.shared.global [%0], [%1], 16;"
                 :: "r"(saddr), "l"(g));
}
#define CP_COMMIT() asm volatile("cp.async.commit_group;" ::: "memory")
#define CP_WAIT0()  asm volatile("cp.async.wait_group 0;" ::: "memory")
#define CP_WAIT1()  asm volatile("cp.async.wait_group 1;" ::: "memory")

// pack (a -> low, b -> high) as bf16x2, plus residual lo pair
__device__ __forceinline__ void split_pair(float a, float b,
                                           uint32_t& hi, uint32_t& lo) {
    uint32_t h;
    asm("cvt.rn.bf16x2.f32 %0, %1, %2;" : "=r"(h) : "f"(b), "f"(a));
    float ha = __uint_as_float(h << 16);
    float hb = __uint_as_float(h & 0xffff0000u);
    uint32_t l;
    asm("cvt.rn.bf16x2.f32 %0, %1, %2;" : "=r"(l) : "f"(b - hb), "f"(a - ha));
    hi = h;
    lo = l;
}

// fp16 variant (for V)
__device__ __forceinline__ void split_pair_f16(float a, float b,
                                               uint32_t& hi, uint32_t& lo) {
    uint32_t h;
    asm("cvt.rn.f16x2.f32 %0, %1, %2;" : "=r"(h) : "f"(b), "f"(a));
    float ha, hb;
    asm("{\n .reg .f16 x, y;\n mov.b32 {x, y}, %2;\n"
        " cvt.f32.f16 %0, x;\n cvt.f32.f16 %1, y;\n}"
        : "=f"(ha), "=f"(hb) : "r"(h));
    asm("cvt.rn.f16x2.f32 %0, %1, %2;" : "=r"(lo) : "f"(b - hb), "f"(a - ha));
    hi = h;
}

// ---------------- lengths ----------------------------------------------------
__global__ void len_kernel(const int* __restrict__ mask) {
    int b = blockIdx.x;
    int t = threadIdx.x;
    int s = 0;
    for (int i = t; i < S; i += 256) s += mask[b*S + i];
    __shared__ int sh[256];
    sh[t] = s;
    __syncthreads();
    for (int o = 128; o > 0; o >>= 1) {
        if (t < o) sh[t] += sh[t + o];
        __syncthreads();
    }
    if (t == 0) g_len[b] = sh[0];
}

// ---------------- fp32 -> bf16 hi/lo decomposition ---------------------------
__global__ __launch_bounds__(256)
void decomp_kernel(const float* __restrict__ x, __nv_bfloat16* __restrict__ hi,
                   __nv_bfloat16* __restrict__ lo, int n4) {
    int i = blockIdx.x * 256 + threadIdx.x;
    if (i >= n4) return;
    float4 v = ((const float4*)x)[i];
    float f[4] = {v.x, v.y, v.z, v.w};
    #pragma unroll
    for (int j = 0; j < 4; j++) {
        __nv_bfloat16 h = __float2bfloat16(f[j]);
        hi[4*i + j] = h;
        lo[4*i + j] = __float2bfloat16(f[j] - __bfloat162float(h));
    }
}

// all 4 weight matrices in one launch; Wq (y==0) pre-scaled by CEXP
__global__ __launch_bounds__(256)
void decompw_kernel(const float* __restrict__ w0, const float* __restrict__ w1,
                    const float* __restrict__ w2, const float* __restrict__ w3,
                    __nv_bfloat16* __restrict__ hi, __nv_bfloat16* __restrict__ lo) {
    int m = blockIdx.y;
    const float* src = (m == 0) ? w0 : (m == 1) ? w1 : (m == 2) ? w2 : w3;
    float sc = (m == 0) ? CEXP : 1.0f;
    int i = blockIdx.x * 256 + threadIdx.x;           // over E*E/4
    float4 v = ((const float4*)src)[i];
    float f[4] = {v.x * sc, v.y * sc, v.z * sc, v.w * sc};
    size_t base = (size_t)m * E * E + 4 * (size_t)i;
    #pragma unroll
    for (int j = 0; j < 4; j++) {
        __nv_bfloat16 h = __float2bfloat16(f[j]);
        hi[base + j] = h;
        lo[base + j] = __float2bfloat16(f[j] - __bfloat162float(h));
    }
}

// ---------------- mma.sync bf16x3 GEMM core (cp.async K=32 pipeline) ---------
// CTA 128x128, 512 threads, warp tile 32x32, 8 chunks of K=32, 2-stage cp.async.
#define GP32 80
#define GCH32 (128 * GP32)                    // 10240 per array
#define GBUF32 (4 * GCH32)                    // 40960 per stage
#define GEMM_SMEM (2 * GBUF32)                // 81920

__device__ __forceinline__ void gemm_core(
    const __nv_bfloat16* __restrict__ Ahi, const __nv_bfloat16* __restrict__ Alo,
    const __nv_bfloat16* __restrict__ Bhi, const __nv_bfloat16* __restrict__ Blo,
    float* __restrict__ Yf,
    __nv_bfloat16* __restrict__ Yhi, __nv_bfloat16* __restrict__ Ylo,
    char* smem, int vfmt) {
    const int bm = blockIdx.x * 128;
    const int bn = blockIdx.y * 128;
    const int tid = threadIdx.x;
    const int lane = tid & 31;
    const int wid = tid >> 5;
    const int wm = (wid & 3) * 32;
    const int wn = (wid >> 2) * 32;
    const uint32_t base = smem_u32(smem);

    float acc[2][4][4];
    #pragma unroll
    for (int mi = 0; mi < 2; mi++)
        #pragma unroll
        for (int ni = 0; ni < 4; ni++)
            #pragma unroll
            for (int k = 0; k < 4; k++) acc[mi][ni][k] = 0.f;

    const int a_row = lane & 15;
    const int a_kb  = (lane >> 4) * 16;
    const int cr = tid >> 2;                  // 0..127
    const int cc = tid & 3;                   // 16B col within 64B row

    #define G_ISSUE(kc, buf) do { \
        uint32_t db = base + (buf) * GBUF32 + cr * GP32 + cc * 16; \
        size_t go = (size_t)cr * E + (kc) * 32 + cc * 8; \
        cpasync16(db,             Ahi + (size_t)bm * E + go); \
        cpasync16(db + GCH32,     Alo + (size_t)bm * E + go); \
        cpasync16(db + 2 * GCH32, Bhi + (size_t)bn * E + go); \
        cpasync16(db + 3 * GCH32, Blo + (size_t)bn * E + go); \
    } while (0)

    G_ISSUE(0, 0); CP_COMMIT();
    G_ISSUE(1, 1); CP_COMMIT();

    for (int kc = 0; kc < 8; kc++) {
        if (kc < 7) CP_WAIT1(); else CP_WAIT0();
        __syncthreads();
        const uint32_t uA = base + (kc & 1) * GBUF32;
        const uint32_t uB = uA + 2 * GCH32;

        #pragma unroll
        for (int ks = 0; ks < 2; ks++) {
            const int kb = ks * 32;
            uint32_t ahi[2][4], alo[2][4], bhi[4][2], blo[4][2];
            #pragma unroll
            for (int mi = 0; mi < 2; mi++) {
                uint32_t off = (uint32_t)((wm + mi * 16 + a_row) * GP32 + kb + a_kb);
                ldsm4(ahi[mi], uA + off);
                ldsm4(alo[mi], uA + GCH32 + off);
            }
            #pragma unroll
            for (int np = 0; np < 2; np++) {
                uint32_t off = (uint32_t)((wn + np * 16 + a_row) * GP32 + kb + a_kb);
                uint32_t th[4], tl[4];
                ldsm4(th, uB + off);
                ldsm4(tl, uB + GCH32 + off);
                bhi[np*2][0] = th[0]; bhi[np*2][1] = th[2];
                bhi[np*2+1][0] = th[1]; bhi[np*2+1][1] = th[3];
                blo[np*2][0] = tl[0]; blo[np*2][1] = tl[2];
                blo[np*2+1][0] = tl[1]; blo[np*2+1][1] = tl[3];
            }
            #pragma unroll
            for (int mi = 0; mi < 2; mi++)
                #pragma unroll
                for (int ni = 0; ni < 4; ni++) {
                    mma16816(acc[mi][ni], ahi[mi], bhi[ni][0], bhi[ni][1]);
                    mma16816(acc[mi][ni], ahi[mi], blo[ni][0], blo[ni][1]);
                    mma16816(acc[mi][ni], alo[mi], bhi[ni][0], bhi[ni][1]);
                }
        }
        __syncthreads();
        if (kc + 2 < 8) { G_ISSUE(kc + 2, kc & 1); CP_COMMIT(); }
    }

    const int g = lane >> 2;
    const int t2 = (lane & 3) * 2;
    #pragma unroll
    for (int mi = 0; mi < 2; mi++)
        #pragma unroll
        for (int ni = 0; ni < 4; ni++) {
            int row = bm + wm + mi * 16 + g;
            int col = bn + wn + ni * 8 + t2;
            if (Yf) {
                *(float2*)&Yf[(size_t)row * E + col] =
                    make_float2(acc[mi][ni][0], acc[mi][ni][1]);
                *(float2*)&Yf[(size_t)(row + 8) * E + col] =
                    make_float2(acc[mi][ni][2], acc[mi][ni][3]);
            } else {
                uint32_t h0, l0, h1, l1;
                if (vfmt) {
                    split_pair_f16(acc[mi][ni][0], acc[mi][ni][1], h0, l0);
                    split_pair_f16(acc[mi][ni][2], acc[mi][ni][3], h1, l1);
                } else {
                    split_pair(acc[mi][ni][0], acc[mi][ni][1], h0, l0);
                    split_pair(acc[mi][ni][2], acc[mi][ni][3], h1, l1);
                }
                *(uint32_t*)(Yhi + (size_t)row * E + col) = h0;
                *(uint32_t*)(Ylo + (size_t)row * E + col) = l0;
                *(uint32_t*)(Yhi + (size_t)(row + 8) * E + col) = h1;
                *(uint32_t*)(Ylo + (size_t)(row + 8) * E + col) = l1;
            }
        }
    #undef G_ISSUE
}

struct QKVOuts {
    __nv_bfloat16 *h0, *l0, *h1, *l1, *h2, *l2;
};

// fused Q/K/V projections: grid.z selects weight + destination; V split in fp16
__global__ __launch_bounds__(512, 1)
void gemm_qkv(const __nv_bfloat16* __restrict__ xhi, const __nv_bfloat16* __restrict__ xlo,
              const __nv_bfloat16* __restrict__ whi, const __nv_bfloat16* __restrict__ wlo,
              QKVOuts o) {
    extern __shared__ char smem[];
    const int z = blockIdx.z;
    const __nv_bfloat16* Bh = whi + (size_t)z * E * E;
    const __nv_bfloat16* Bl = wlo + (size_t)z * E * E;
    __nv_bfloat16* Yh = (z == 0) ? o.h0 : (z == 1) ? o.h1 : o.h2;
    __nv_bfloat16* Yl = (z == 0) ? o.l0 : (z == 1) ? o.l1 : o.l2;
    gemm_core(xhi, xlo, Bh, Bl, nullptr, Yh, Yl, smem, z == 2);
}

__global__ __launch_bounds__(512, 1)
void gemm_out(const __nv_bfloat16* __restrict__ phi, const __nv_bfloat16* __restrict__ plo,
              const __nv_bfloat16* __restrict__ whi, const __nv_bfloat16* __restrict__ wlo,
              float* __restrict__ Yf) {
    extern __shared__ char smem[];
    gemm_core(phi, plo, whi, wlo, Yf, nullptr, nullptr, smem, 0);
}

// ---------------- tensor-core varlen flash attention --------------------------
// CTA: 128 queries of one (b,h); 4 warps x 32 q-rows; key tiles of 64.
// K bf16 hi/lo; V fp16 hi/lo; P single fp16. Fixed-base softmax p = 2^s.
#define PQ 80
#define SM_KV (2 * 128 * PQ)                  // Q region: 20480
#define KVBUF (256 * PQ)                      // Khi|Klo|Vhi|Vlo, 64 rows each
#define ATTN_SMEM (SM_KV + 2 * KVBUF)         // 61440

__global__ __launch_bounds__(128, 2)
void attn_mma() {
    const int b = blockIdx.z;
    const int h = blockIdx.y;
    const int L = g_len[b];
    const int qt = blockIdx.x * 128;
    if (qt >= L) return;

    extern __shared__ char sm[];
    const uint32_t uQh = smem_u32(sm);

    const int tid = threadIdx.x;
    const int lane = tid & 31;
    const int w = tid >> 5;
    const int wq = w * 32;
    const int g = lane >> 2;
    const int t2 = (lane & 3) * 2;

    const int pr = tid >> 2;
    const int pc = tid & 3;

    #define KV_ISSUE(k0, buf) do { \
        uint32_t dbase = uQh + SM_KV + (buf) * KVBUF; \
        _Pragma("unroll") \
        for (int i = 0; i < 8; i++) { \
            int r = pr + i * 32; \
            int region = r >> 6, rr = r & 63; \
            const __nv_bfloat16* src = \
                (region == 0) ? g_khi : (region == 1) ? g_klo : \
                (region == 2) ? g_vhi : g_vlo; \
            cpasync16(dbase + r * PQ + pc * 16, \
                      src + ((size_t)(b * S + (k0) + rr)) * E + h * D + pc * 8); \
        } \
    } while (0)

    // ---- stage Q tile (128 rows x 32 cols = 64B/row, hi+lo) ----
    {
        int r = tid;
        size_t off = ((size_t)(b * S + qt + r)) * E + h * D;
        const uint4* sh = (const uint4*)(g_qhi + off);
        const uint4* sl = (const uint4*)(g_qlo + off);
        #pragma unroll
        for (int j = 0; j < 4; j++) {
            *(uint4*)(sm + r * PQ + 16 * j)            = sh[j];
            *(uint4*)(sm + 128 * PQ + r * PQ + 16 * j) = sl[j];
        }
    }
    KV_ISSUE(0, 0);
    CP_COMMIT();
    __syncthreads();

    // Q fragments (kept in registers for the whole kernel)
    uint32_t qh[2][2][4], ql[2][2][4];
    #pragma unroll
    for (int mi = 0; mi < 2; mi++)
        #pragma unroll
        for (int s = 0; s < 2; s++) {
            uint32_t ad = uQh + (wq + mi * 16 + (lane & 15)) * PQ
                        + (lane >> 4) * 16 + s * 32;
            ldsm4(qh[mi][s], ad);
            ldsm4(ql[mi][s], ad + 128 * PQ);
        }

    float lsum[2][2], acc[2][4][4];
    #pragma unroll
    for (int mi = 0; mi < 2; mi++)
        #pragma unroll
        for (int hf = 0; hf < 2; hf++) lsum[mi][hf] = 0.f;
    #pragma unroll
    for (int mi = 0; mi < 2; mi++)
        #pragma unroll
        for (int nd = 0; nd < 4; nd++)
            #pragma unroll
            for (int c = 0; c < 4; c++) acc[mi][nd][c] = 0.f;

    const int ntiles = (L + 63) >> 6;
    for (int t = 0; t < ntiles; t++) {
        const int tn = min(64, L - t * 64);
        if (t + 1 < ntiles) {
            KV_ISSUE((t + 1) * 64, (t + 1) & 1);
            CP_COMMIT();
            CP_WAIT1();
        } else {
            CP_WAIT0();
        }
        __syncthreads();

        const uint32_t uK = uQh + SM_KV + (t & 1) * KVBUF;       // Khi
        const uint32_t uV = uK + 128 * PQ;                        // Vhi

        // ---- scores: S[32q x 64k] per warp, bf16x3 compensated ----
        float sc[2][8][4];
        #pragma unroll
        for (int mi = 0; mi < 2; mi++)
            #pragma unroll
            for (int nj = 0; nj < 8; nj++)
                #pragma unroll
                for (int c = 0; c < 4; c++) sc[mi][nj][c] = 0.f;

        #pragma unroll
        for (int njp = 0; njp < 4; njp++) {
            uint32_t kh[2][4], kl[2][4];
            #pragma unroll
            for (int s = 0; s < 2; s++) {
                uint32_t ad = uK + (njp * 16 + (lane & 15)) * PQ
                            + (lane >> 4) * 16 + s * 32;
                ldsm4(kh[s], ad);
                ldsm4(kl[s], ad + 64 * PQ);
            }
            #pragma unroll
            for (int mi = 0; mi < 2; mi++)
                #pragma unroll
                for (int j2 = 0; j2 < 2; j2++) {
                    float* dst = sc[mi][njp * 2 + j2];
                    #pragma unroll
                    for (int s = 0; s < 2; s++) {
                        mma16816(dst, qh[mi][s], kh[s][j2], kh[s][2 + j2]);
                        mma16816(dst, qh[mi][s], kl[s][j2], kl[s][2 + j2]);
                        mma16816(dst, ql[mi][s], kh[s][j2], kh[s][2 + j2]);
                    }
                }
        }

        // ---- mask tail keys ----
        if (tn < 64) {
            #pragma unroll
            for (int mi = 0; mi < 2; mi++)
                #pragma unroll
                for (int nj = 0; nj < 8; nj++)
                    #pragma unroll
                    for (int c = 0; c < 4; c++) {
                        int kc = nj * 8 + t2 + (c & 1);
                        if (kc >= tn) sc[mi][nj][c] = -1e30f;
                    }
        }

        // ---- fixed-base softmax: p = 2^s (no max subtraction) ----
        #pragma unroll
        for (int mi = 0; mi < 2; mi++)
            #pragma unroll
            for (int hf = 0; hf < 2; hf++) {
                float rowsum = 0.f;
                #pragma unroll
                for (int nj = 0; nj < 8; nj++) {
                    float p0 = ex2(sc[mi][nj][hf * 2]);
                    float p1 = ex2(sc[mi][nj][hf * 2 + 1]);
                    sc[mi][nj][hf * 2] = p0;
                    sc[mi][nj][hf * 2 + 1] = p1;
                    rowsum += p0 + p1;
                }
                rowsum += __shfl_xor_sync(0xffffffffu, rowsum, 1);
                rowsum += __shfl_xor_sync(0xffffffffu, rowsum, 2);
                lsum[mi][hf] += rowsum;
            }

        // ---- PV: O += P * V; P single fp16, V fp16 hi/lo (2-term) ----
        #pragma unroll
        for (int s = 0; s < 4; s++) {          // k16 steps
            uint32_t ph[2][4];
            #pragma unroll
            for (int mi = 0; mi < 2; mi++) {
                float* c0 = sc[mi][2 * s];
                float* c1 = sc[mi][2 * s + 1];
                asm("cvt.rn.f16x2.f32 %0, %1, %2;" : "=r"(ph[mi][0]) : "f"(c0[1]), "f"(c0[0]));
                asm("cvt.rn.f16x2.f32 %0, %1, %2;" : "=r"(ph[mi][1]) : "f"(c0[3]), "f"(c0[2]));
                asm("cvt.rn.f16x2.f32 %0, %1, %2;" : "=r"(ph[mi][2]) : "f"(c1[1]), "f"(c1[0]));
                asm("cvt.rn.f16x2.f32 %0, %1, %2;" : "=r"(ph[mi][3]) : "f"(c1[3]), "f"(c1[2]));
            }
            #pragma unroll
            for (int dp = 0; dp < 2; dp++) {   // d-octet pairs
                uint32_t ad = uV + (s * 16 + (lane & 7) + ((lane >> 3) & 1) * 8) * PQ
                            + dp * 32 + (lane >> 4) * 16;
                uint32_t vh[4], vl[4];
                ldsm4t(vh, ad);
                ldsm4t(vl, ad + 64 * PQ);
                #pragma unroll
                for (int mi = 0; mi < 2; mi++) {
                    mma16816h(acc[mi][2*dp],   ph[mi], vh[0], vh[1]);
                    mma16816h(acc[mi][2*dp],   ph[mi], vl[0], vl[1]);
                    mma16816h(acc[mi][2*dp+1], ph[mi], vh[2], vh[3]);
                    mma16816h(acc[mi][2*dp+1], ph[mi], vl[2], vl[3]);
                }
            }
        }
        __syncthreads();                       // buffer reuse safety
    }

    // ---- epilogue: O/l, bf16 hi/lo split, scrambled-layout write ----
    #pragma unroll
    for (int mi = 0; mi < 2; mi++)
        #pragma unroll
        for (int hf = 0; hf < 2; hf++) {
            int q = qt + wq + mi * 16 + g + hf * 8;
            if (q < L) {
                float inv = 1.f / lsum[mi][hf];
                #pragma unroll
                for (int nd = 0; nd < 4; nd++) {
                    float o0 = acc[mi][nd][hf * 2] * inv;
                    float o1 = acc[mi][nd][hf * 2 + 1] * inv;
                    uint32_t hh, ll;
                    split_pair(o0, o1, hh, ll);
                    size_t off = (size_t)b * S * E + ((size_t)h * L + q) * D
                               + nd * 8 + t2;
                    *(uint32_t*)(g_phi + off) = hh;
                    *(uint32_t*)(g_plo + off) = ll;
                }
            }
        }
    #undef KV_ISSUE
}

// ---------------- launch ------------------------------------------------------
extern "C" void kernel_launch(void* const* d_in, const int* in_sizes, int n_in,
                              void* d_out, int out_size) {
    const float* x    = (const float*)d_in[0];
    const int*   mask = (const int*)  d_in[1];
    const float* Wq   = (const float*)d_in[2];
    const float* Wk   = (const float*)d_in[3];
    const float* Wv   = (const float*)d_in[4];
    const float* Wo   = (const float*)d_in[5];
    float* out = (float*)d_out;

    __nv_bfloat16 *xhi, *xlo, *qhi, *qlo, *khi, *klo, *vhi, *vlo, *phi, *plo, *whi, *wlo;
    cudaGetSymbolAddress((void**)&xhi, g_xhi);
    cudaGetSymbolAddress((void**)&xlo, g_xlo);
    cudaGetSymbolAddress((void**)&qhi, g_qhi);
    cudaGetSymbolAddress((void**)&qlo, g_qlo);
    cudaGetSymbolAddress((void**)&khi, g_khi);
    cudaGetSymbolAddress((void**)&klo, g_klo);
    cudaGetSymbolAddress((void**)&vhi, g_vhi);
    cudaGetSymbolAddress((void**)&vlo, g_vlo);
    cudaGetSymbolAddress((void**)&phi, g_phi);
    cudaGetSymbolAddress((void**)&plo, g_plo);
    cudaGetSymbolAddress((void**)&whi, g_whi);
    cudaGetSymbolAddress((void**)&wlo, g_wlo);

    cudaFuncSetAttribute(gemm_qkv, cudaFuncAttributeMaxDynamicSharedMemorySize,
                         GEMM_SMEM);
    cudaFuncSetAttribute(gemm_out, cudaFuncAttributeMaxDynamicSharedMemorySize,
                         GEMM_SMEM);
    cudaFuncSetAttribute(attn_mma, cudaFuncAttributeMaxDynamicSharedMemorySize,
                         ATTN_SMEM);

    len_kernel<<<B, 256>>>(mask);
    cudaMemsetAsync(phi, 0, (size_t)M * E * sizeof(__nv_bfloat16), 0);
    cudaMemsetAsync(plo, 0, (size_t)M * E * sizeof(__nv_bfloat16), 0);

    decomp_kernel<<<(M*E/4 + 255)/256, 256>>>(x, xhi, xlo, M*E/4);
    decompw_kernel<<<dim3(E*E/4/256, 4), 256>>>(Wq, Wk, Wv, Wo, whi, wlo);

    QKVOuts o = { qhi, qlo, khi, klo, vhi, vlo };
    dim3 gq(M / 128, E / 128, 3);
    gemm_qkv<<<gq, 512, GEMM_SMEM>>>(xhi, xlo, whi, wlo, o);

    dim3 ga(S / 128, H, B);
    attn_mma<<<ga, 128, ATTN_SMEM>>>();

    dim3 gg(M / 128, E / 128);
    gemm_out<<<gg, 512, GEMM_SMEM>>>(phi, plo, whi + 3*E*E, wlo + 3*E*E, out);
}

// round 10
// speedup vs baseline: 6.2042x; 1.3519x over previous
#include <cuda_runtime.h>
#include <cuda_fp16.h>
#include <stdint.h>

#define B 4
#define S 2048
#define E 256
#define H 8
#define D 32
#define M (B*S)
// SCALE * log2(e), folded into Wq at decomposition time
#define CEXP (0.17677669529663687f * 1.44269504088896341f)

// ---------------- scratch (device globals; no allocation allowed) ----------
static __device__ __align__(16) __half g_x16[M*E];
static __device__ __align__(16) __half g_q16[M*E];
static __device__ __align__(16) __half g_khi[M*E];
static __device__ __align__(16) __half g_klo[M*E];
static __device__ __align__(16) __half g_vhi[M*E];
static __device__ __align__(16) __half g_vlo[M*E];
static __device__ __align__(16) __half g_p16[M*E];
static __device__ __align__(16) __half g_whi[4*E*E];
static __device__ __align__(16) __half g_wlo[4*E*E];
static __device__ int g_len[B];

// ---------------- helpers ----------------------------------------------------
__device__ __forceinline__ uint32_t smem_u32(const void* p) {
    uint32_t a;
    asm("{ .reg .u64 t; cvta.to.shared.u64 t, %1; cvt.u32.u64 %0, t; }"
        : "=r"(a) : "l"(p));
    return a;
}

__device__ __forceinline__ void ldsm4(uint32_t* r, uint32_t addr) {
    asm volatile("ldmatrix.sync.aligned.m8n8.x4.shared.b16 {%0,%1,%2,%3}, [%4];"
                 : "=r"(r[0]), "=r"(r[1]), "=r"(r[2]), "=r"(r[3]) : "r"(addr));
}

__device__ __forceinline__ void ldsm4t(uint32_t* r, uint32_t addr) {
    asm volatile("ldmatrix.sync.aligned.m8n8.x4.trans.shared.b16 {%0,%1,%2,%3}, [%4];"
                 : "=r"(r[0]), "=r"(r[1]), "=r"(r[2]), "=r"(r[3]) : "r"(addr));
}

// fp16 MMA
__device__ __forceinline__ void mma16816h(float* d, const uint32_t* a,
                                          uint32_t b0, uint32_t b1) {
    asm volatile(
        "mma.sync.aligned.m16n8k16.row.col.f32.f16.f16.f32 "
        "{%0,%1,%2,%3}, {%4,%5,%6,%7}, {%8,%9}, {%0,%1,%2,%3};"
        : "+f"(d[0]), "+f"(d[1]), "+f"(d[2]), "+f"(d[3])
        : "r"(a[0]), "r"(a[1]), "r"(a[2]), "r"(a[3]), "r"(b0), "r"(b1));
}

__device__ __forceinline__ float ex2(float x) {
    float y;
    asm("ex2.approx.ftz.f32 %0, %1;" : "=f"(y) : "f"(x));
    return y;
}

__device__ __forceinline__ void cpasync16(uint32_t saddr, const void* g) {
    asm volatile("cp.async.cg.shared.global [%0], [%1], 16;"
                 :: "r"(saddr), "l"(g));
}
#define CP_COMMIT() asm volatile("cp.async.commit_group;" ::: "memory")
#define CP_WAIT0()  asm volatile("cp.async.wait_group 0;" ::: "memory")
#define CP_WAIT1()  asm volatile("cp.async.wait_group 1;" ::: "memory")

// fp16 pack helpers
__device__ __forceinline__ uint32_t pack_f16(float a, float b) {
    uint32_t h;
    asm("cvt.rn.f16x2.f32 %0, %1, %2;" : "=r"(h) : "f"(b), "f"(a));
    return h;
}
__device__ __forceinline__ void split_pair_f16(float a, float b,
                                               uint32_t& hi, uint32_t& lo) {
    uint32_t h = pack_f16(a, b);
    float ha, hb;
    asm("{\n .reg .f16 x, y;\n mov.b32 {x, y}, %2;\n"
        " cvt.f32.f16 %0, x;\n cvt.f32.f16 %1, y;\n}"
        : "=f"(ha), "=f"(hb) : "r"(h));
    lo = pack_f16(a - ha, b - hb);
    hi = h;
}

// ---------------- lengths ----------------------------------------------------
__global__ void len_kernel(const int* __restrict__ mask) {
    int b = blockIdx.x;
    int t = threadIdx.x;
    int s = 0;
    for (int i = t; i < S; i += 256) s += mask[b*S + i];
    __shared__ int sh[256];
    sh[t] = s;
    __syncthreads();
    for (int o = 128; o > 0; o >>= 1) {
        if (t < o) sh[t] += sh[t + o];
        __syncthreads();
    }
    if (t == 0) g_len[b] = sh[0];
}

// ---------------- fp32 -> fp16 single (x) -------------------------------------
__global__ __launch_bounds__(256)
void decomp_kernel(const float* __restrict__ x, __half* __restrict__ o, int n4) {
    int i = blockIdx.x * 256 + threadIdx.x;
    if (i >= n4) return;
    float4 v = ((const float4*)x)[i];
    uint32_t* d = (uint32_t*)(o + 4 * (size_t)i);
    d[0] = pack_f16(v.x, v.y);
    d[1] = pack_f16(v.z, v.w);
}

// all 4 weight matrices, fp16 hi/lo; Wq (y==0) pre-scaled by CEXP
__global__ __launch_bounds__(256)
void decompw_kernel(const float* __restrict__ w0, const float* __restrict__ w1,
                    const float* __restrict__ w2, const float* __restrict__ w3,
                    __half* __restrict__ hi, __half* __restrict__ lo) {
    int m = blockIdx.y;
    const float* src = (m == 0) ? w0 : (m == 1) ? w1 : (m == 2) ? w2 : w3;
    float sc = (m == 0) ? CEXP : 1.0f;
    int i = blockIdx.x * 256 + threadIdx.x;           // over E*E/4
    float4 v = ((const float4*)src)[i];
    float f[4] = {v.x * sc, v.y * sc, v.z * sc, v.w * sc};
    size_t base = (size_t)m * E * E + 4 * (size_t)i;
    uint32_t h0, l0, h1, l1;
    split_pair_f16(f[0], f[1], h0, l0);
    split_pair_f16(f[2], f[3], h1, l1);
    *(uint32_t*)(hi + base) = h0;  *(uint32_t*)(hi + base + 2) = h1;
    *(uint32_t*)(lo + base) = l0;  *(uint32_t*)(lo + base + 2) = l1;
}

// ---------------- fp16x2 GEMM core: Y[m,n] = sum_k X[m,k] W[n,k] -------------
// A single fp16, W fp16 hi/lo (2-term). CTA 128x128, 512 threads, warp 32x32,
// K chunks of 64 double-buffered via register prefetch (R8-proven staging).
#define GPITCH 144
#define GCHUNKB (128 * GPITCH)
#define GBUFB (3 * GCHUNKB)                    // A | Bh | Bl
#define GEMM_SMEM (2 * GBUFB)                  // 110592

__device__ __forceinline__ void gemm_core(
    const __half* __restrict__ Ah,
    const __half* __restrict__ Bhi, const __half* __restrict__ Blo,
    float* __restrict__ Yf,
    __half* __restrict__ Yhi, __half* __restrict__ Ylo,
    char* smem, int mode) {            // mode: 0=fp32, 1=fp16 hi/lo, 2=fp16 single
    const int bm = blockIdx.x * 128;
    const int bn = blockIdx.y * 128;
    const int tid = threadIdx.x;
    const int lane = tid & 31;
    const int wid = tid >> 5;
    const int wm = (wid & 3) * 32;
    const int wn = (wid >> 2) * 32;
    const uint32_t base = smem_u32(smem);

    float acc[2][4][4];
    #pragma unroll
    for (int mi = 0; mi < 2; mi++)
        #pragma unroll
        for (int ni = 0; ni < 4; ni++)
            #pragma unroll
            for (int k = 0; k < 4; k++) acc[mi][ni][k] = 0.f;

    const int a_row = lane & 15;
    const int a_kb  = (lane >> 4) * 16;
    const int pr0 = tid >> 3, pc0 = tid & 7;
    const int pr1 = (tid + 512) >> 3, pc1 = (tid + 512) & 7;

    float4 pf[6];
    #define PFLOAD(k0) do { \
        size_t g0 = (size_t)pr0 * E + (k0) + pc0 * 8; \
        size_t g1 = (size_t)pr1 * E + (k0) + pc1 * 8; \
        pf[0] = *(const float4*)(Ah  + (size_t)bm * E + g0); \
        pf[1] = *(const float4*)(Bhi + (size_t)bn * E + g0); \
        pf[2] = *(const float4*)(Blo + (size_t)bn * E + g0); \
        pf[3] = *(const float4*)(Ah  + (size_t)bm * E + g1); \
        pf[4] = *(const float4*)(Bhi + (size_t)bn * E + g1); \
        pf[5] = *(const float4*)(Blo + (size_t)bn * E + g1); \
    } while (0)
    #define PFSTORE(buf) do { \
        char* bp = smem + (buf) * GBUFB; \
        int s0 = pr0 * GPITCH + pc0 * 16; \
        int s1 = pr1 * GPITCH + pc1 * 16; \
        *(float4*)(bp + s0)               = pf[0]; \
        *(float4*)(bp + GCHUNKB + s0)     = pf[1]; \
        *(float4*)(bp + 2 * GCHUNKB + s0) = pf[2]; \
        *(float4*)(bp + s1)               = pf[3]; \
        *(float4*)(bp + GCHUNKB + s1)     = pf[4]; \
        *(float4*)(bp + 2 * GCHUNKB + s1) = pf[5]; \
    } while (0)

    PFLOAD(0);
    PFSTORE(0);
    __syncthreads();

    for (int kc = 0; kc < 4; kc++) {
        if (kc < 3) PFLOAD((kc + 1) * 64);
        const uint32_t uA = base + (kc & 1) * GBUFB;
        const uint32_t uB = uA + GCHUNKB;

        #pragma unroll
        for (int ks = 0; ks < 4; ks++) {
            const int kb = ks * 32;
            uint32_t a[2][4], bhi[4][2], blo[4][2];
            #pragma unroll
            for (int mi = 0; mi < 2; mi++) {
                uint32_t off = (uint32_t)((wm + mi * 16 + a_row) * GPITCH + kb + a_kb);
                ldsm4(a[mi], uA + off);
            }
            #pragma unroll
            for (int np = 0; np < 2; np++) {
                uint32_t off = (uint32_t)((wn + np * 16 + a_row) * GPITCH + kb + a_kb);
                uint32_t th[4], tl[4];
                ldsm4(th, uB + off);
                ldsm4(tl, uB + GCHUNKB + off);
                bhi[np*2][0] = th[0]; bhi[np*2][1] = th[2];
                bhi[np*2+1][0] = th[1]; bhi[np*2+1][1] = th[3];
                blo[np*2][0] = tl[0]; blo[np*2][1] = tl[2];
                blo[np*2+1][0] = tl[1]; blo[np*2+1][1] = tl[3];
            }
            #pragma unroll
            for (int mi = 0; mi < 2; mi++)
                #pragma unroll
                for (int ni = 0; ni < 4; ni++) {
                    mma16816h(acc[mi][ni], a[mi], bhi[ni][0], bhi[ni][1]);
                    mma16816h(acc[mi][ni], a[mi], blo[ni][0], blo[ni][1]);
                }
        }
        if (kc < 3) {
            PFSTORE((kc + 1) & 1);
            __syncthreads();
        }
    }

    const int g = lane >> 2;
    const int t2 = (lane & 3) * 2;
    #pragma unroll
    for (int mi = 0; mi < 2; mi++)
        #pragma unroll
        for (int ni = 0; ni < 4; ni++) {
            int row = bm + wm + mi * 16 + g;
            int col = bn + wn + ni * 8 + t2;
            float* ac = acc[mi][ni];
            if (mode == 0) {
                *(float2*)&Yf[(size_t)row * E + col] = make_float2(ac[0], ac[1]);
                *(float2*)&Yf[(size_t)(row + 8) * E + col] = make_float2(ac[2], ac[3]);
            } else if (mode == 2) {
                *(uint32_t*)(Yhi + (size_t)row * E + col) = pack_f16(ac[0], ac[1]);
                *(uint32_t*)(Yhi + (size_t)(row + 8) * E + col) = pack_f16(ac[2], ac[3]);
            } else {
                uint32_t h0, l0, h1, l1;
                split_pair_f16(ac[0], ac[1], h0, l0);
                split_pair_f16(ac[2], ac[3], h1, l1);
                *(uint32_t*)(Yhi + (size_t)row * E + col) = h0;
                *(uint32_t*)(Ylo + (size_t)row * E + col) = l0;
                *(uint32_t*)(Yhi + (size_t)(row + 8) * E + col) = h1;
                *(uint32_t*)(Ylo + (size_t)(row + 8) * E + col) = l1;
            }
        }
    #undef PFLOAD
    #undef PFSTORE
}

struct QKVOuts {
    __half *q, *kh, *kl, *vh, *vl;
};

// fused Q/K/V projections: z=0 Q (single fp16), z=1 K (hi/lo), z=2 V (hi/lo)
__global__ __launch_bounds__(512, 1)
void gemm_qkv(const __half* __restrict__ x16,
              const __half* __restrict__ whi, const __half* __restrict__ wlo,
              QKVOuts o) {
    extern __shared__ char smem[];
    const int z = blockIdx.z;
    const __half* Bh = whi + (size_t)z * E * E;
    const __half* Bl = wlo + (size_t)z * E * E;
    if (z == 0)
        gemm_core(x16, Bh, Bl, nullptr, o.q, nullptr, smem, 2);
    else if (z == 1)
        gemm_core(x16, Bh, Bl, nullptr, o.kh, o.kl, smem, 1);
    else
        gemm_core(x16, Bh, Bl, nullptr, o.vh, o.vl, smem, 1);
}

__global__ __launch_bounds__(512, 1)
void gemm_out(const __half* __restrict__ p16,
              const __half* __restrict__ whi, const __half* __restrict__ wlo,
              float* __restrict__ Yf) {
    extern __shared__ char smem[];
    gemm_core(p16, whi, wlo, Yf, nullptr, nullptr, smem, 0);
}

// ---------------- tensor-core varlen flash attention --------------------------
// CTA: 128 queries of one (b,h); 4 warps x 32 q-rows; key tiles of 64.
// Q single fp16; K fp16 hi/lo (2-term QK); V fp16 hi/lo; P single fp16.
// Fixed-base softmax p = 2^s. cp.async double-buffered K/V.
#define PQ 80
#define SM_KV (128 * PQ)                      // Q region: 10240
#define KVBUF (256 * PQ)                      // Khi|Klo|Vhi|Vlo, 64 rows each
#define ATTN_SMEM (SM_KV + 2 * KVBUF)         // 51200

__global__ __launch_bounds__(128, 2)
void attn_mma() {
    const int b = blockIdx.z;
    const int h = blockIdx.y;
    const int L = g_len[b];
    const int qt = blockIdx.x * 128;
    if (qt >= L) return;

    extern __shared__ char sm[];
    const uint32_t uQh = smem_u32(sm);

    const int tid = threadIdx.x;
    const int lane = tid & 31;
    const int w = tid >> 5;
    const int wq = w * 32;
    const int g = lane >> 2;
    const int t2 = (lane & 3) * 2;

    const int pr = tid >> 2;
    const int pc = tid & 3;

    #define KV_ISSUE(k0, buf) do { \
        uint32_t dbase = uQh + SM_KV + (buf) * KVBUF; \
        _Pragma("unroll") \
        for (int i = 0; i < 8; i++) { \
            int r = pr + i * 32; \
            int region = r >> 6, rr = r & 63; \
            const __half* src = \
                (region == 0) ? g_khi : (region == 1) ? g_klo : \
                (region == 2) ? g_vhi : g_vlo; \
            cpasync16(dbase + r * PQ + pc * 16, \
                      src + ((size_t)(b * S + (k0) + rr)) * E + h * D + pc * 8); \
        } \
    } while (0)

    // ---- stage Q tile (128 rows x 64B, single fp16) ----
    {
        int r = tid;
        size_t off = ((size_t)(b * S + qt + r)) * E + h * D;
        const uint4* sh = (const uint4*)(g_q16 + off);
        #pragma unroll
        for (int j = 0; j < 4; j++)
            *(uint4*)(sm + r * PQ + 16 * j) = sh[j];
    }
    KV_ISSUE(0, 0);
    CP_COMMIT();
    __syncthreads();

    // Q fragments (kept in registers for the whole kernel)
    uint32_t qh[2][2][4];
    #pragma unroll
    for (int mi = 0; mi < 2; mi++)
        #pragma unroll
        for (int s = 0; s < 2; s++) {
            uint32_t ad = uQh + (wq + mi * 16 + (lane & 15)) * PQ
                        + (lane >> 4) * 16 + s * 32;
            ldsm4(qh[mi][s], ad);
        }

    float lsum[2][2], acc[2][4][4];
    #pragma unroll
    for (int mi = 0; mi < 2; mi++)
        #pragma unroll
        for (int hf = 0; hf < 2; hf++) lsum[mi][hf] = 0.f;
    #pragma unroll
    for (int mi = 0; mi < 2; mi++)
        #pragma unroll
        for (int nd = 0; nd < 4; nd++)
            #pragma unroll
            for (int c = 0; c < 4; c++) acc[mi][nd][c] = 0.f;

    const int ntiles = (L + 63) >> 6;
    for (int t = 0; t < ntiles; t++) {
        const int tn = min(64, L - t * 64);
        if (t + 1 < ntiles) {
            KV_ISSUE((t + 1) * 64, (t + 1) & 1);
            CP_COMMIT();
            CP_WAIT1();
        } else {
            CP_WAIT0();
        }
        __syncthreads();

        const uint32_t uK = uQh + SM_KV + (t & 1) * KVBUF;       // Khi
        const uint32_t uV = uK + 128 * PQ;                        // Vhi

        // ---- scores: S[32q x 64k] per warp; Q single x K hi/lo (2 terms) ----
        float sc[2][8][4];
        #pragma unroll
        for (int mi = 0; mi < 2; mi++)
            #pragma unroll
            for (int nj = 0; nj < 8; nj++)
                #pragma unroll
                for (int c = 0; c < 4; c++) sc[mi][nj][c] = 0.f;

        #pragma unroll
        for (int njp = 0; njp < 4; njp++) {
            uint32_t kh[2][4], kl[2][4];
            #pragma unroll
            for (int s = 0; s < 2; s++) {
                uint32_t ad = uK + (njp * 16 + (lane & 15)) * PQ
                            + (lane >> 4) * 16 + s * 32;
                ldsm4(kh[s], ad);
                ldsm4(kl[s], ad + 64 * PQ);
            }
            #pragma unroll
            for (int mi = 0; mi < 2; mi++)
                #pragma unroll
                for (int j2 = 0; j2 < 2; j2++) {
                    float* dst = sc[mi][njp * 2 + j2];
                    #pragma unroll
                    for (int s = 0; s < 2; s++) {
                        mma16816h(dst, qh[mi][s], kh[s][j2], kh[s][2 + j2]);
                        mma16816h(dst, qh[mi][s], kl[s][j2], kl[s][2 + j2]);
                    }
                }
        }

        // ---- mask tail keys ----
        if (tn < 64) {
            #pragma unroll
            for (int mi = 0; mi < 2; mi++)
                #pragma unroll
                for (int nj = 0; nj < 8; nj++)
                    #pragma unroll
                    for (int c = 0; c < 4; c++) {
                        int kc = nj * 8 + t2 + (c & 1);
                        if (kc >= tn) sc[mi][nj][c] = -1e30f;
                    }
        }

        // ---- fixed-base softmax: p = 2^s ----
        #pragma unroll
        for (int mi = 0; mi < 2; mi++)
            #pragma unroll
            for (int hf = 0; hf < 2; hf++) {
                float rowsum = 0.f;
                #pragma unroll
                for (int nj = 0; nj < 8; nj++) {
                    float p0 = ex2(sc[mi][nj][hf * 2]);
                    float p1 = ex2(sc[mi][nj][hf * 2 + 1]);
                    sc[mi][nj][hf * 2] = p0;
                    sc[mi][nj][hf * 2 + 1] = p1;
                    rowsum += p0 + p1;
                }
                rowsum += __shfl_xor_sync(0xffffffffu, rowsum, 1);
                rowsum += __shfl_xor_sync(0xffffffffu, rowsum, 2);
                lsum[mi][hf] += rowsum;
            }

        // ---- PV: O += P * V; P single fp16, V fp16 hi/lo (2-term) ----
        #pragma unroll
        for (int s = 0; s < 4; s++) {          // k16 steps
            uint32_t ph[2][4];
            #pragma unroll
            for (int mi = 0; mi < 2; mi++) {
                float* c0 = sc[mi][2 * s];
                float* c1 = sc[mi][2 * s + 1];
                ph[mi][0] = pack_f16(c0[0], c0[1]);
                ph[mi][1] = pack_f16(c0[2], c0[3]);
                ph[mi][2] = pack_f16(c1[0], c1[1]);
                ph[mi][3] = pack_f16(c1[2], c1[3]);
            }
            #pragma unroll
            for (int dp = 0; dp < 2; dp++) {   // d-octet pairs
                uint32_t ad = uV + (s * 16 + (lane & 7) + ((lane >> 3) & 1) * 8) * PQ
                            + dp * 32 + (lane >> 4) * 16;
                uint32_t vh[4], vl[4];
                ldsm4t(vh, ad);
                ldsm4t(vl, ad + 64 * PQ);
                #pragma unroll
                for (int mi = 0; mi < 2; mi++) {
                    mma16816h(acc[mi][2*dp],   ph[mi], vh[0], vh[1]);
                    mma16816h(acc[mi][2*dp],   ph[mi], vl[0], vl[1]);
                    mma16816h(acc[mi][2*dp+1], ph[mi], vh[2], vh[3]);
                    mma16816h(acc[mi][2*dp+1], ph[mi], vl[2], vl[3]);
                }
            }
        }
        __syncthreads();                       // buffer reuse safety
    }

    // ---- epilogue: O/l, single fp16, scrambled-layout write ----
    #pragma unroll
    for (int mi = 0; mi < 2; mi++)
        #pragma unroll
        for (int hf = 0; hf < 2; hf++) {
            int q = qt + wq + mi * 16 + g + hf * 8;
            if (q < L) {
                float inv = 1.f / lsum[mi][hf];
                #pragma unroll
                for (int nd = 0; nd < 4; nd++) {
                    float o0 = acc[mi][nd][hf * 2] * inv;
                    float o1 = acc[mi][nd][hf * 2 + 1] * inv;
                    size_t off = (size_t)b * S * E + ((size_t)h * L + q) * D
                               + nd * 8 + t2;
                    *(uint32_t*)(g_p16 + off) = pack_f16(o0, o1);
                }
            }
        }
    #undef KV_ISSUE
}

// ---------------- launch ------------------------------------------------------
extern "C" void kernel_launch(void* const* d_in, const int* in_sizes, int n_in,
                              void* d_out, int out_size) {
    const float* x    = (const float*)d_in[0];
    const int*   mask = (const int*)  d_in[1];
    const float* Wq   = (const float*)d_in[2];
    const float* Wk   = (const float*)d_in[3];
    const float* Wv   = (const float*)d_in[4];
    const float* Wo   = (const float*)d_in[5];
    float* out = (float*)d_out;

    __half *x16, *q16, *khi, *klo, *vhi, *vlo, *p16, *whi, *wlo;
    cudaGetSymbolAddress((void**)&x16, g_x16);
    cudaGetSymbolAddress((void**)&q16, g_q16);
    cudaGetSymbolAddress((void**)&khi, g_khi);
    cudaGetSymbolAddress((void**)&klo, g_klo);
    cudaGetSymbolAddress((void**)&vhi, g_vhi);
    cudaGetSymbolAddress((void**)&vlo, g_vlo);
    cudaGetSymbolAddress((void**)&p16, g_p16);
    cudaGetSymbolAddress((void**)&whi, g_whi);
    cudaGetSymbolAddress((void**)&wlo, g_wlo);

    cudaFuncSetAttribute(gemm_qkv, cudaFuncAttributeMaxDynamicSharedMemorySize,
                         GEMM_SMEM);
    cudaFuncSetAttribute(gemm_out, cudaFuncAttributeMaxDynamicSharedMemorySize,
                         GEMM_SMEM);
    cudaFuncSetAttribute(attn_mma, cudaFuncAttributeMaxDynamicSharedMemorySize,
                         ATTN_SMEM);

    len_kernel<<<B, 256>>>(mask);
    cudaMemsetAsync(p16, 0, (size_t)M * E * sizeof(__half), 0);

    decomp_kernel<<<(M*E/4 + 255)/256, 256>>>(x, x16, M*E/4);
    decompw_kernel<<<dim3(E*E/4/256, 4), 256>>>(Wq, Wk, Wv, Wo, whi, wlo);

    QKVOuts o = { q16, khi, klo, vhi, vlo };
    dim3 gq(M / 128, E / 128, 3);
    gemm_qkv<<<gq, 512, GEMM_SMEM>>>(x16, whi, wlo, o);

    dim3 ga(S / 128, H, B);
    attn_mma<<<ga, 128, ATTN_SMEM>>>();

    dim3 gg(M / 128, E / 128);
    gemm_out<<<gg, 512, GEMM_SMEM>>>(p16, whi + 3*E*E, wlo + 3*E*E, out);
}